// round 1
// baseline (speedup 1.0000x reference)
#include <cuda_runtime.h>
#include <cuda_bf16.h>
#include <cstdint>

// ---------------------------------------------------------------------------
// RPN pipeline: conv3x3(256->256) -> 1x1 heads -> decode -> sort -> NMS
// ---------------------------------------------------------------------------

#define FEAT_W 52
#define NPIX   (FEAT_W * FEAT_W)          // 2704
#define CIN    256
#define COUT   256
#define KTOT   (9 * CIN)                  // 2304
#define NANCH  9
#define NROWS  (NPIX * NANCH)             // 24336
#define KEYPAD 24352                      // NROWS padded to mult of 16
#define PRE_NMS 12000
#define NPAD    12032                     // PRE_NMS padded to mult of 64
#define NWORDS  188                       // NPAD/64
#define POST_NMS 2000
#define IMG_WF 210.0f
#define MIN_SIZE 16.0f
#define NMS_T 0.7f

// output layout (floats)
#define OFF_ROIS 0
#define OFF_LOCS 8000
#define OFF_CLS  105344
#define OFF_OBJ  154016
#define OFF_CLS2 178352

// -------------------- scratch (__device__ globals; no allocs) --------------
__device__ float  g_Wt[KTOT * COUT];          // k-major transposed weights
__device__ float  g_h[NPIX * COUT];           // conv1 output, pixel-major
__device__ float4 g_roi[NROWS];               // decoded clipped boxes
__device__ int    g_valid[NROWS];
__device__ unsigned long long g_key[KEYPAD];  // sortable keys
__device__ float4 g_sorted[NPAD];             // top-12000 boxes by score
__device__ unsigned long long g_suppInit[NWORDS];

// ---------------------------------------------------------------------------
// Kernel A: transpose conv1_w (OIHW, O=256,I=256,3,3) -> Wt[k][oc],
// k = (ky*3+kx)*256 + c
// ---------------------------------------------------------------------------
__global__ void k_transpose(const float* __restrict__ w) {
    int idx = blockIdx.x * blockDim.x + threadIdx.x;
    if (idx >= KTOT * COUT) return;
    int oc = idx / KTOT;          // coalesced read over j
    int j  = idx % KTOT;          // j = c*9 + ki
    int c  = j / 9;
    int ki = j % 9;
    g_Wt[(ki * CIN + c) * COUT + oc] = w[idx];
}

// ---------------------------------------------------------------------------
// Kernel B: conv1 3x3 SAME as tiled implicit GEMM.
// C[p][oc] = sum_k A[p][k]*Wt[k][oc],  A[p][k] = x[c, y+ky-1, x+kx-1]
// BM=BN=64, BK=16, 256 threads, 4x4 micro-tile.
// ---------------------------------------------------------------------------
__global__ void __launch_bounds__(256) k_conv1(const float* __restrict__ X,
                                               const float* __restrict__ bias) {
    __shared__ float As[16 * 64];
    __shared__ float Bs[16 * 64];

    int m0 = blockIdx.x * 64;
    int n0 = blockIdx.y * 64;
    int tid = threadIdx.x;
    int tx = tid & 15;
    int ty = tid >> 4;

    // precompute pixel coords for the 4 A-tile elements this thread loads
    int py[4], px[4], pm[4];
    #pragma unroll
    for (int r = 0; r < 4; r++) {
        int e  = tid + 256 * r;
        int mm = e & 63;
        int p  = m0 + mm;
        pm[r] = mm;
        if (p < NPIX) { py[r] = p / FEAT_W; px[r] = p % FEAT_W; }
        else          { py[r] = -1000; px[r] = -1000; }
    }

    float acc[4][4];
    #pragma unroll
    for (int i = 0; i < 4; i++)
        #pragma unroll
        for (int j = 0; j < 4; j++) acc[i][j] = 0.0f;

    for (int kt = 0; kt < KTOT; kt += 16) {
        int ki = kt >> 8;           // 0..8 (constant within a 16-wide k-tile)
        int dy = ki / 3 - 1;
        int dx = ki % 3 - 1;
        int cbase = kt & 255;

        #pragma unroll
        for (int r = 0; r < 4; r++) {
            int e  = tid + 256 * r;
            int kk = e >> 6;
            int iy = py[r] + dy;
            int ix = px[r] + dx;
            float v = 0.0f;
            if (iy >= 0 && iy < FEAT_W && ix >= 0 && ix < FEAT_W)
                v = X[(cbase + kk) * NPIX + iy * FEAT_W + ix];
            As[kk * 64 + pm[r]] = v;
        }
        #pragma unroll
        for (int r = 0; r < 4; r++) {
            int e  = tid + 256 * r;
            int nn = e & 63;
            int kk = e >> 6;
            Bs[kk * 64 + nn] = g_Wt[(kt + kk) * COUT + n0 + nn];
        }
        __syncthreads();

        #pragma unroll
        for (int kk = 0; kk < 16; kk++) {
            float a[4], b[4];
            #pragma unroll
            for (int i = 0; i < 4; i++) a[i] = As[kk * 64 + ty + 16 * i];
            #pragma unroll
            for (int j = 0; j < 4; j++) b[j] = Bs[kk * 64 + tx + 16 * j];
            #pragma unroll
            for (int i = 0; i < 4; i++)
                #pragma unroll
                for (int j = 0; j < 4; j++)
                    acc[i][j] = fmaf(a[i], b[j], acc[i][j]);
        }
        __syncthreads();
    }

    #pragma unroll
    for (int i = 0; i < 4; i++) {
        int p = m0 + ty + 16 * i;
        if (p >= NPIX) continue;
        #pragma unroll
        for (int j = 0; j < 4; j++) {
            int n = n0 + tx + 16 * j;
            g_h[p * COUT + n] = acc[i][j] + bias[n];
        }
    }
}

// ---------------------------------------------------------------------------
// Kernel C: per-pixel heads (36 reg + 18 cls dots), outputs, decode, keys.
// One block per pixel, 64 threads.
// ---------------------------------------------------------------------------
__global__ void __launch_bounds__(64) k_head(const float* __restrict__ reg_w,
                                             const float* __restrict__ reg_b,
                                             const float* __restrict__ cls_w,
                                             const float* __restrict__ cls_b,
                                             float* __restrict__ out) {
    __shared__ float hsh[256];
    __shared__ float sv[54];

    int p = blockIdx.x;
    int y = p / FEAT_W;
    int xp = p % FEAT_W;
    int tid = threadIdx.x;

    for (int c = tid; c < 256; c += 64) hsh[c] = g_h[p * COUT + c];
    __syncthreads();

    if (tid < 54) {
        const float* w;
        float b;
        if (tid < 36) { w = reg_w + tid * 256; b = reg_b[tid]; }
        else          { w = cls_w + (tid - 36) * 256; b = cls_b[tid - 36]; }
        float acc = 0.0f;
        #pragma unroll 8
        for (int c = 0; c < 256; c++) acc = fmaf(w[c], hsh[c], acc);
        sv[tid] = acc + b;
    }
    __syncthreads();

    if (tid < NANCH) {
        int a = tid;
        int row = p * NANCH + a;
        float l0 = sv[a * 4 + 0], l1 = sv[a * 4 + 1];
        float l2 = sv[a * 4 + 2], l3 = sv[a * 4 + 3];
        float c0 = sv[36 + a * 2 + 0];
        float c1 = sv[36 + a * 2 + 1];

        float* locs = out + OFF_LOCS;
        float* clsO = out + OFF_CLS;
        float* objO = out + OFF_OBJ;
        float* cls2 = out + OFF_CLS2;
        locs[row * 4 + 0] = l0; locs[row * 4 + 1] = l1;
        locs[row * 4 + 2] = l2; locs[row * 4 + 3] = l3;
        clsO[row * 2 + 0] = c0; clsO[row * 2 + 1] = c1;
        cls2[row * 2 + 0] = c0; cls2[row * 2 + 1] = c1;
        objO[row] = c1;

        // anchors: fp64 like the reference, then cast to f32
        const double sr [3] = {0.7071067811865476, 1.0, 1.4142135623730951};
        const double sri[3] = {1.4142135623730951, 1.0, 0.7071067811865476};
        const double sc [3] = {4.0, 8.0, 16.0};
        double h2 = 2.0 * sc[a % 3] * sr [a / 3];
        double w2 = 2.0 * sc[a % 3] * sri[a / 3];
        double cyd = 4.0 * y + 2.0;
        double cxd = 4.0 * xp + 2.0;
        float y1 = (float)(cyd - h2), x1 = (float)(cxd - w2);
        float y2 = (float)(cyd + h2), x2 = (float)(cxd + w2);

        float ah = y2 - y1, aw = x2 - x1;
        float acy = fmaf(0.5f, ah, y1), acx = fmaf(0.5f, aw, x1);
        float dcy = fmaf(l0, ah, acy),  dcx = fmaf(l1, aw, acx);
        float hh = expf(l2) * ah, ww = expf(l3) * aw;
        float ry1 = fmaf(-0.5f, hh, dcy), rx1 = fmaf(-0.5f, ww, dcx);
        float ry2 = fmaf( 0.5f, hh, dcy), rx2 = fmaf( 0.5f, ww, dcx);
        ry1 = fminf(fmaxf(ry1, 0.0f), IMG_WF);
        rx1 = fminf(fmaxf(rx1, 0.0f), IMG_WF);
        ry2 = fminf(fmaxf(ry2, 0.0f), IMG_WF);
        rx2 = fminf(fmaxf(rx2, 0.0f), IMG_WF);
        float hs = ry2 - ry1, ws = rx2 - rx1;
        int valid = (hs >= MIN_SIZE) && (ws >= MIN_SIZE);

        g_roi[row] = make_float4(ry1, rx1, ry2, rx2);
        g_valid[row] = valid;

        float sc_m = valid ? c1 : __int_as_float(0xff800000);
        unsigned int u = __float_as_uint(sc_m);
        unsigned int k32 = u ^ ((u & 0x80000000u) ? 0xFFFFFFFFu : 0x80000000u);
        unsigned int dk = ~k32;  // ascending dk == descending score
        g_key[row] = ((unsigned long long)dk << 32) | (unsigned int)row;
    }
}

// ---------------------------------------------------------------------------
// Kernel I: init supp words + key padding
// ---------------------------------------------------------------------------
__global__ void k_init() {
    int t = threadIdx.x;
    if (t < NWORDS)
        g_suppInit[t] = (t == NWORDS - 1) ? 0xFFFFFFFF00000000ull : 0ull;
    if (t < KEYPAD - NROWS) g_key[NROWS + t] = ~0ull;
}

// ---------------------------------------------------------------------------
// Kernel D: O(N^2) rank sort (keys resident in smem, broadcast compare loop)
// ---------------------------------------------------------------------------
__global__ void __launch_bounds__(1024) k_rank() {
    extern __shared__ unsigned long long sk[];
    int tid = threadIdx.x;
    for (int i = tid; i < KEYPAD; i += 1024) sk[i] = g_key[i];
    __syncthreads();

    int idx = blockIdx.x * 1024 + tid;
    if (idx >= NROWS) return;
    unsigned long long mykey = sk[idx];
    int r = 0;
    #pragma unroll 8
    for (int j = 0; j < KEYPAD; j++) r += (sk[j] < mykey);
    if (r < PRE_NMS) {
        g_sorted[r] = g_roi[idx];
        if (!g_valid[idx])
            atomicOr(&g_suppInit[r >> 6], 1ull << (r & 63));
    }
}

// ---------------------------------------------------------------------------
// Kernel E: one-block greedy NMS (64-box groups) + output scatter
// ---------------------------------------------------------------------------
struct NmsSmem {
    float4 B[NPAD];
    unsigned long long supp[NWORDS];
    unsigned long long gmask[64];
    unsigned long long sCur;
    int sKept;
    int cnts[NWORDS + 1];
};

__device__ __forceinline__ float box_area(float4 b) {
    return (b.w - b.y + 1.0f) * (b.z - b.x + 1.0f);
}
__device__ __forceinline__ bool iou_gt(float4 a, float aa, float4 b, float ab) {
    float yy1 = fmaxf(a.x, b.x), xx1 = fmaxf(a.y, b.y);
    float yy2 = fminf(a.z, b.z), xx2 = fminf(a.w, b.w);
    float inter = fmaxf(0.0f, xx2 - xx1 + 1.0f) * fmaxf(0.0f, yy2 - yy1 + 1.0f);
    float iou = inter / (aa + ab - inter);
    return iou > NMS_T;
}

__global__ void __launch_bounds__(1024) k_nms(float* __restrict__ out) {
    extern __shared__ char raw[];
    NmsSmem* S = (NmsSmem*)raw;
    int tid = threadIdx.x;

    for (int i = tid; i < NPAD; i += 1024)
        S->B[i] = (i < PRE_NMS) ? g_sorted[i] : make_float4(0.f, 0.f, 0.f, 0.f);
    for (int w = tid; w < NWORDS; w += 1024) S->supp[w] = g_suppInit[w];
    if (tid == 0) S->sKept = 0;
    __syncthreads();

    int gEnd = NWORDS - 1;
    for (int g = 0; g < NWORDS; g++) {
        int i0 = g * 64;
        if (tid < 64) S->gmask[tid] = 0ull;
        __syncthreads();

        unsigned long long sg = S->supp[g];
        // intra-group IoU mask (j > l only), parallel over the block
        for (int idx = tid; idx < 4096; idx += 1024) {
            int l = idx >> 6, j = idx & 63;
            if (j > l && !((sg >> l) & 1ull) && !((sg >> j) & 1ull)) {
                float4 bl = S->B[i0 + l];
                float4 bj = S->B[i0 + j];
                if (iou_gt(bl, box_area(bl), bj, box_area(bj)))
                    atomicOr(&S->gmask[l], 1ull << j);
            }
        }
        __syncthreads();

        if (tid == 0) {  // serial greedy resolve inside the group
            unsigned long long s = sg;
            #pragma unroll 4
            for (int l = 0; l < 64; l++)
                if (!((s >> l) & 1ull)) s |= S->gmask[l];
            S->supp[g] = s;
            S->sKept += __popcll(~s);
            S->sCur = ~s;
        }
        __syncthreads();

        if (S->sKept >= POST_NMS) { gEnd = g; break; }

        unsigned long long cm = S->sCur;
        if (cm) {  // suppress later boxes against this group's survivors
            for (int j = i0 + 64 + tid; j < NPAD; j += 1024) {
                int w = j >> 6;
                if ((S->supp[w] >> (j & 63)) & 1ull) continue;
                float4 bj = S->B[j];
                float aj = box_area(bj);
                unsigned long long m = cm;
                while (m) {
                    int l = __ffsll((long long)m) - 1;
                    m &= m - 1;
                    float4 bl = S->B[i0 + l];
                    if (iou_gt(bl, box_area(bl), bj, aj)) {
                        atomicOr(&S->supp[w], 1ull << (j & 63));
                        break;
                    }
                }
            }
        }
        __syncthreads();
    }
    __syncthreads();

    // scatter first min(kept, 2000) boxes; zero the rest
    for (int w = tid; w < NWORDS; w += 1024)
        S->cnts[w] = (w <= gEnd) ? __popcll(~S->supp[w]) : 0;
    __syncthreads();
    if (tid == 0) {
        int run = 0;
        for (int w = 0; w < NWORDS; w++) { int c = S->cnts[w]; S->cnts[w] = run; run += c; }
        S->cnts[NWORDS] = run;
    }
    __syncthreads();

    float* rois = out + OFF_ROIS;
    for (int w = tid; w < NWORDS; w += 1024) {
        if (w > gEnd) continue;
        unsigned long long k = ~S->supp[w];
        int r = S->cnts[w];
        while (k) {
            int b = __ffsll((long long)k) - 1;
            k &= k - 1;
            if (r < POST_NMS) {
                float4 bx = S->B[w * 64 + b];
                rois[r * 4 + 0] = bx.x; rois[r * 4 + 1] = bx.y;
                rois[r * 4 + 2] = bx.z; rois[r * 4 + 3] = bx.w;
            }
            r++;
        }
    }
    int total = min(S->cnts[NWORDS], POST_NMS);
    for (int i = total * 4 + tid; i < POST_NMS * 4; i += 1024) rois[i] = 0.0f;
}

// ---------------------------------------------------------------------------
extern "C" void kernel_launch(void* const* d_in, const int* in_sizes, int n_in,
                              void* d_out, int out_size) {
    const float* x       = (const float*)d_in[0];
    const float* conv1_w = (const float*)d_in[1];
    const float* conv1_b = (const float*)d_in[2];
    const float* reg_w   = (const float*)d_in[3];
    const float* reg_b   = (const float*)d_in[4];
    const float* cls_w   = (const float*)d_in[5];
    const float* cls_b   = (const float*)d_in[6];
    float* out = (float*)d_out;

    size_t rankSmem = (size_t)KEYPAD * sizeof(unsigned long long);
    size_t nmsSmem  = sizeof(NmsSmem);
    cudaFuncSetAttribute(k_rank, cudaFuncAttributeMaxDynamicSharedMemorySize, (int)rankSmem);
    cudaFuncSetAttribute(k_nms,  cudaFuncAttributeMaxDynamicSharedMemorySize, (int)nmsSmem);

    k_transpose<<<(KTOT * COUT + 255) / 256, 256>>>(conv1_w);
    k_conv1<<<dim3((NPIX + 63) / 64, COUT / 64), 256>>>(x, conv1_b);
    k_head<<<NPIX, 64>>>(reg_w, reg_b, cls_w, cls_b, out);
    k_init<<<1, 256>>>();
    k_rank<<<(NROWS + 1023) / 1024, 1024, rankSmem>>>();
    k_nms<<<1, 1024, nmsSmem>>>(out);
}

// round 2
// speedup vs baseline: 4.9505x; 4.9505x over previous
#include <cuda_runtime.h>
#include <cuda_bf16.h>
#include <cstdint>

// ---------------------------------------------------------------------------
// RPN pipeline: conv3x3(256->256) -> 1x1 heads -> decode -> sort -> bitmask NMS
// ---------------------------------------------------------------------------

#define FEAT_W 52
#define NPIX   (FEAT_W * FEAT_W)          // 2704
#define CIN    256
#define COUT   256
#define KTOT   (9 * CIN)                  // 2304
#define NANCH  9
#define NROWS  (NPIX * NANCH)             // 24336
#define KEYPAD 24352                      // NROWS padded to mult of 16
#define PRE_NMS 12000
#define NPAD    12032                     // PRE_NMS padded to mult of 64
#define NWORDS  188                       // NPAD/64
#define POST_NMS 2000
#define IMG_WF 210.0f
#define MIN_SIZE 16.0f
#define NMS_T 0.7f

// output layout (floats)
#define OFF_ROIS 0
#define OFF_LOCS 8000
#define OFF_CLS  105344
#define OFF_OBJ  154016
#define OFF_CLS2 178352

// -------------------- scratch (__device__ globals; no allocs) --------------
__device__ float  g_Wt[KTOT * COUT];          // k-major transposed weights
__device__ float  g_h[NPIX * COUT];           // conv1 output, pixel-major
__device__ float4 g_roi[NROWS];               // decoded clipped boxes
__device__ int    g_valid[NROWS];
__device__ unsigned long long g_key[KEYPAD];  // sortable keys
__device__ float4 g_sorted[NPAD];             // top-12000 boxes by score
__device__ unsigned long long g_suppInit[NWORDS];
__device__ unsigned long long g_mask[(size_t)NPAD * NWORDS];  // 18.1 MB IoU bitmask

// ---------------------------------------------------------------------------
// Kernel A: transpose conv1_w (OIHW) -> Wt[k][oc], k = (ky*3+kx)*256 + c
// ---------------------------------------------------------------------------
__global__ void k_transpose(const float* __restrict__ w) {
    int idx = blockIdx.x * blockDim.x + threadIdx.x;
    if (idx >= KTOT * COUT) return;
    int oc = idx / KTOT;
    int j  = idx % KTOT;
    int c  = j / 9;
    int ki = j % 9;
    g_Wt[(ki * CIN + c) * COUT + oc] = w[idx];
}

// ---------------------------------------------------------------------------
// Kernel B: conv1 3x3 SAME as tiled implicit GEMM. BM=BN=64, BK=16, 4x4 micro.
// ---------------------------------------------------------------------------
__global__ void __launch_bounds__(256) k_conv1(const float* __restrict__ X,
                                               const float* __restrict__ bias) {
    __shared__ float As[16 * 64];
    __shared__ float Bs[16 * 64];

    int m0 = blockIdx.x * 64;
    int n0 = blockIdx.y * 64;
    int tid = threadIdx.x;
    int tx = tid & 15;
    int ty = tid >> 4;

    int py[4], px[4], pm[4];
    #pragma unroll
    for (int r = 0; r < 4; r++) {
        int e  = tid + 256 * r;
        int mm = e & 63;
        int p  = m0 + mm;
        pm[r] = mm;
        if (p < NPIX) { py[r] = p / FEAT_W; px[r] = p % FEAT_W; }
        else          { py[r] = -1000; px[r] = -1000; }
    }

    float acc[4][4];
    #pragma unroll
    for (int i = 0; i < 4; i++)
        #pragma unroll
        for (int j = 0; j < 4; j++) acc[i][j] = 0.0f;

    for (int kt = 0; kt < KTOT; kt += 16) {
        int ki = kt >> 8;
        int dy = ki / 3 - 1;
        int dx = ki % 3 - 1;
        int cbase = kt & 255;

        #pragma unroll
        for (int r = 0; r < 4; r++) {
            int e  = tid + 256 * r;
            int kk = e >> 6;
            int iy = py[r] + dy;
            int ix = px[r] + dx;
            float v = 0.0f;
            if (iy >= 0 && iy < FEAT_W && ix >= 0 && ix < FEAT_W)
                v = X[(cbase + kk) * NPIX + iy * FEAT_W + ix];
            As[kk * 64 + pm[r]] = v;
        }
        #pragma unroll
        for (int r = 0; r < 4; r++) {
            int e  = tid + 256 * r;
            int nn = e & 63;
            int kk = e >> 6;
            Bs[kk * 64 + nn] = g_Wt[(kt + kk) * COUT + n0 + nn];
        }
        __syncthreads();

        #pragma unroll
        for (int kk = 0; kk < 16; kk++) {
            float a[4], b[4];
            #pragma unroll
            for (int i = 0; i < 4; i++) a[i] = As[kk * 64 + ty + 16 * i];
            #pragma unroll
            for (int j = 0; j < 4; j++) b[j] = Bs[kk * 64 + tx + 16 * j];
            #pragma unroll
            for (int i = 0; i < 4; i++)
                #pragma unroll
                for (int j = 0; j < 4; j++)
                    acc[i][j] = fmaf(a[i], b[j], acc[i][j]);
        }
        __syncthreads();
    }

    #pragma unroll
    for (int i = 0; i < 4; i++) {
        int p = m0 + ty + 16 * i;
        if (p >= NPIX) continue;
        #pragma unroll
        for (int j = 0; j < 4; j++) {
            int n = n0 + tx + 16 * j;
            g_h[p * COUT + n] = acc[i][j] + bias[n];
        }
    }
}

// ---------------------------------------------------------------------------
// Kernel C: per-pixel heads + decode + sortable keys
// ---------------------------------------------------------------------------
__global__ void __launch_bounds__(64) k_head(const float* __restrict__ reg_w,
                                             const float* __restrict__ reg_b,
                                             const float* __restrict__ cls_w,
                                             const float* __restrict__ cls_b,
                                             float* __restrict__ out) {
    __shared__ float hsh[256];
    __shared__ float sv[54];

    int p = blockIdx.x;
    int y = p / FEAT_W;
    int xp = p % FEAT_W;
    int tid = threadIdx.x;

    for (int c = tid; c < 256; c += 64) hsh[c] = g_h[p * COUT + c];
    __syncthreads();

    if (tid < 54) {
        const float* w;
        float b;
        if (tid < 36) { w = reg_w + tid * 256; b = reg_b[tid]; }
        else          { w = cls_w + (tid - 36) * 256; b = cls_b[tid - 36]; }
        float acc = 0.0f;
        #pragma unroll 8
        for (int c = 0; c < 256; c++) acc = fmaf(w[c], hsh[c], acc);
        sv[tid] = acc + b;
    }
    __syncthreads();

    if (tid < NANCH) {
        int a = tid;
        int row = p * NANCH + a;
        float l0 = sv[a * 4 + 0], l1 = sv[a * 4 + 1];
        float l2 = sv[a * 4 + 2], l3 = sv[a * 4 + 3];
        float c0 = sv[36 + a * 2 + 0];
        float c1 = sv[36 + a * 2 + 1];

        float* locs = out + OFF_LOCS;
        float* clsO = out + OFF_CLS;
        float* objO = out + OFF_OBJ;
        float* cls2 = out + OFF_CLS2;
        locs[row * 4 + 0] = l0; locs[row * 4 + 1] = l1;
        locs[row * 4 + 2] = l2; locs[row * 4 + 3] = l3;
        clsO[row * 2 + 0] = c0; clsO[row * 2 + 1] = c1;
        cls2[row * 2 + 0] = c0; cls2[row * 2 + 1] = c1;
        objO[row] = c1;

        const double sr [3] = {0.7071067811865476, 1.0, 1.4142135623730951};
        const double sri[3] = {1.4142135623730951, 1.0, 0.7071067811865476};
        const double sc [3] = {4.0, 8.0, 16.0};
        double h2 = 2.0 * sc[a % 3] * sr [a / 3];
        double w2 = 2.0 * sc[a % 3] * sri[a / 3];
        double cyd = 4.0 * y + 2.0;
        double cxd = 4.0 * xp + 2.0;
        float y1 = (float)(cyd - h2), x1 = (float)(cxd - w2);
        float y2 = (float)(cyd + h2), x2 = (float)(cxd + w2);

        float ah = y2 - y1, aw = x2 - x1;
        float acy = fmaf(0.5f, ah, y1), acx = fmaf(0.5f, aw, x1);
        float dcy = fmaf(l0, ah, acy),  dcx = fmaf(l1, aw, acx);
        float hh = expf(l2) * ah, ww = expf(l3) * aw;
        float ry1 = fmaf(-0.5f, hh, dcy), rx1 = fmaf(-0.5f, ww, dcx);
        float ry2 = fmaf( 0.5f, hh, dcy), rx2 = fmaf( 0.5f, ww, dcx);
        ry1 = fminf(fmaxf(ry1, 0.0f), IMG_WF);
        rx1 = fminf(fmaxf(rx1, 0.0f), IMG_WF);
        ry2 = fminf(fmaxf(ry2, 0.0f), IMG_WF);
        rx2 = fminf(fmaxf(rx2, 0.0f), IMG_WF);
        float hs = ry2 - ry1, ws = rx2 - rx1;
        int valid = (hs >= MIN_SIZE) && (ws >= MIN_SIZE);

        g_roi[row] = make_float4(ry1, rx1, ry2, rx2);
        g_valid[row] = valid;

        float sc_m = valid ? c1 : __int_as_float(0xff800000);
        unsigned int u = __float_as_uint(sc_m);
        unsigned int k32 = u ^ ((u & 0x80000000u) ? 0xFFFFFFFFu : 0x80000000u);
        unsigned int dk = ~k32;  // ascending dk == descending score
        g_key[row] = ((unsigned long long)dk << 32) | (unsigned int)row;
    }
}

// ---------------------------------------------------------------------------
// Kernel I: init supp words + key padding (re-run every replay)
// ---------------------------------------------------------------------------
__global__ void k_init() {
    int t = threadIdx.x;
    if (t < NWORDS)
        g_suppInit[t] = (t == NWORDS - 1) ? 0xFFFFFFFF00000000ull : 0ull;
    if (t < KEYPAD - NROWS) g_key[NROWS + t] = ~0ull;
}

// ---------------------------------------------------------------------------
// Kernel D: O(N^2) rank sort (keys resident in smem, broadcast compare loop)
// ---------------------------------------------------------------------------
__global__ void __launch_bounds__(1024) k_rank() {
    extern __shared__ unsigned long long sk[];
    int tid = threadIdx.x;
    for (int i = tid; i < KEYPAD; i += 1024) sk[i] = g_key[i];
    __syncthreads();

    int idx = blockIdx.x * 1024 + tid;
    if (idx >= NROWS) return;
    unsigned long long mykey = sk[idx];
    int r = 0;
    #pragma unroll 8
    for (int j = 0; j < KEYPAD; j++) r += (sk[j] < mykey);
    if (r < PRE_NMS) {
        g_sorted[r] = g_roi[idx];
        if (!g_valid[idx])
            atomicOr(&g_suppInit[r >> 6], 1ull << (r & 63));
    }
}

// ---------------------------------------------------------------------------
// IoU helpers (identical arithmetic to round-1 passing version)
// ---------------------------------------------------------------------------
__device__ __forceinline__ float box_area(float4 b) {
    return (b.w - b.y + 1.0f) * (b.z - b.x + 1.0f);
}
__device__ __forceinline__ bool iou_gt(float4 a, float aa, float4 b, float ab) {
    float yy1 = fmaxf(a.x, b.x), xx1 = fmaxf(a.y, b.y);
    float yy2 = fminf(a.z, b.z), xx2 = fminf(a.w, b.w);
    float inter = fmaxf(0.0f, xx2 - xx1 + 1.0f) * fmaxf(0.0f, yy2 - yy1 + 1.0f);
    float iou = inter / (aa + ab - inter);
    return iou > NMS_T;
}

// ---------------------------------------------------------------------------
// Kernel E1: pairwise IoU bitmask matrix.
// block (c, r): 64 rows [64r..) x 64 cols [64c..), only c >= r computed.
// g_mask[i][w] = bitmask over j in word w with j > i and IoU(i,j) > 0.7
// ---------------------------------------------------------------------------
__global__ void __launch_bounds__(256) k_mask() {
    __shared__ float4 RB[64], CB[64];
    __shared__ float  RA[64], CA[64];
    __shared__ unsigned long long MW[64];

    int c = blockIdx.x;   // column word
    int r = blockIdx.y;   // row group
    if (c < r) return;
    int tid = threadIdx.x;

    if (tid < 64) {
        float4 b = g_sorted[r * 64 + tid];
        RB[tid] = b; RA[tid] = box_area(b);
        MW[tid] = 0ull;
    } else if (tid < 128) {
        int t = tid - 64;
        float4 b = g_sorted[c * 64 + t];
        CB[t] = b; CA[t] = box_area(b);
    }
    __syncthreads();

    int l  = tid >> 2;          // row 0..63
    int j0 = (tid & 3) * 16;    // 16 cols per thread
    int gi = r * 64 + l;
    float4 bl = RB[l];
    float  al = RA[l];
    unsigned long long bits = 0ull;
    #pragma unroll
    for (int jj = 0; jj < 16; jj++) {
        int j  = j0 + jj;
        int gj = c * 64 + j;
        if (gj > gi && iou_gt(bl, al, CB[j], CA[j]))
            bits |= 1ull << j;
    }
    if (bits) atomicOr(&MW[l], bits);
    __syncthreads();

    if (tid < 64)
        g_mask[(size_t)(r * 64 + tid) * NWORDS + c] = MW[tid];
}

// ---------------------------------------------------------------------------
// Kernel E2: greedy bitmask reduce (== reference lax.scan) + output scatter.
// One block. Per 64-row word: prefetch 64 diagonal words, thread0 resolves
// serially in registers, then 256 threads OR kept rows into later words.
// ---------------------------------------------------------------------------
__global__ void __launch_bounds__(256) k_reduce(float* __restrict__ out) {
    __shared__ unsigned long long removed[NWORDS];
    __shared__ unsigned long long diag[64];
    __shared__ int keepList[POST_NMS];
    __shared__ int kcount;
    __shared__ unsigned long long keptSh;

    int tid = threadIdx.x;
    for (int w = tid; w < NWORDS; w += 256) removed[w] = g_suppInit[w];
    if (tid == 0) kcount = 0;
    __syncthreads();

    for (int w = 0; w < NWORDS; w++) {
        if (kcount >= POST_NMS) break;

        if (tid < 64)
            diag[tid] = g_mask[(size_t)(w * 64 + tid) * NWORDS + w];
        __syncthreads();

        if (tid == 0) {
            unsigned long long rm = removed[w];
            unsigned long long kept = 0ull;
            int kc = kcount;
            for (int b = 0; b < 64 && kc < POST_NMS; b++) {
                if (!((rm >> b) & 1ull)) {
                    keepList[kc++] = w * 64 + b;
                    kept |= 1ull << b;
                    rm |= diag[b];
                }
            }
            removed[w] = rm;
            kcount = kc;
            keptSh = kept;
        }
        __syncthreads();

        unsigned long long kept = keptSh;
        if (kept) {
            for (int w2 = w + 1 + tid; w2 < NWORDS; w2 += 256) {
                unsigned long long acc = 0ull;
                unsigned long long m = kept;
                while (m) {
                    int b = __ffsll((long long)m) - 1;
                    m &= m - 1;
                    acc |= g_mask[(size_t)(w * 64 + b) * NWORDS + w2];
                }
                removed[w2] |= acc;
            }
        }
        __syncthreads();
    }

    int total = kcount;  // <= POST_NMS
    float* rois = out + OFF_ROIS;
    for (int k = tid; k < total; k += 256) {
        float4 bx = g_sorted[keepList[k]];
        rois[k * 4 + 0] = bx.x; rois[k * 4 + 1] = bx.y;
        rois[k * 4 + 2] = bx.z; rois[k * 4 + 3] = bx.w;
    }
    for (int i = total * 4 + tid; i < POST_NMS * 4; i += 256)
        rois[i] = 0.0f;
}

// ---------------------------------------------------------------------------
extern "C" void kernel_launch(void* const* d_in, const int* in_sizes, int n_in,
                              void* d_out, int out_size) {
    const float* x       = (const float*)d_in[0];
    const float* conv1_w = (const float*)d_in[1];
    const float* conv1_b = (const float*)d_in[2];
    const float* reg_w   = (const float*)d_in[3];
    const float* reg_b   = (const float*)d_in[4];
    const float* cls_w   = (const float*)d_in[5];
    const float* cls_b   = (const float*)d_in[6];
    float* out = (float*)d_out;

    size_t rankSmem = (size_t)KEYPAD * sizeof(unsigned long long);
    cudaFuncSetAttribute(k_rank, cudaFuncAttributeMaxDynamicSharedMemorySize, (int)rankSmem);

    k_transpose<<<(KTOT * COUT + 255) / 256, 256>>>(conv1_w);
    k_conv1<<<dim3((NPIX + 63) / 64, COUT / 64), 256>>>(x, conv1_b);
    k_head<<<NPIX, 64>>>(reg_w, reg_b, cls_w, cls_b, out);
    k_init<<<1, 256>>>();
    k_rank<<<(NROWS + 1023) / 1024, 1024, rankSmem>>>();
    k_mask<<<dim3(NWORDS, NWORDS), 256>>>();
    k_reduce<<<1, 256>>>(out);
}

// round 3
// speedup vs baseline: 6.7402x; 1.3615x over previous
#include <cuda_runtime.h>
#include <cuda_bf16.h>
#include <cstdint>

// ---------------------------------------------------------------------------
// RPN pipeline: conv3x3(256->256) -> 1x1 heads -> decode -> sort -> bitmask NMS
// ---------------------------------------------------------------------------

#define FEAT_W 52
#define NPIX   (FEAT_W * FEAT_W)          // 2704
#define CIN    256
#define COUT   256
#define KTOT   (9 * CIN)                  // 2304
#define NANCH  9
#define NROWS  (NPIX * NANCH)             // 24336
#define PRE_NMS 12000
#define NPAD    12032                     // PRE_NMS padded to mult of 64
#define NWORDS  188                       // NPAD/64
#define POST_NMS 2000
#define IMG_WF 210.0f
#define MIN_SIZE 16.0f
#define NMS_T 0.7f

// output layout (floats)
#define OFF_ROIS 0
#define OFF_LOCS 8000
#define OFF_CLS  105344
#define OFF_OBJ  154016
#define OFF_CLS2 178352

// -------------------- scratch (__device__ globals; no allocs) --------------
__device__ float  g_Wt[KTOT * COUT];          // k-major transposed weights
__device__ float  g_h[NPIX * COUT];           // conv1 output, pixel-major
__device__ float4 g_roi[NROWS];               // decoded clipped boxes
__device__ int    g_valid[NROWS];
__device__ unsigned long long g_key[NROWS];   // sortable keys (unique)
__device__ int    g_rank[NROWS];              // partial rank accumulators
__device__ float4 g_sorted[NPAD];             // top-12000 boxes by score
__device__ unsigned long long g_suppInit[NWORDS];
__device__ unsigned long long g_mask[(size_t)NPAD * NWORDS];  // 18.1 MB IoU bitmask

// -------------------- f32x2 packed-FMA helpers -----------------------------
__device__ __forceinline__ void ffma2(unsigned long long& d,
                                      unsigned long long a,
                                      unsigned long long b) {
    asm("fma.rn.f32x2 %0, %1, %2, %0;" : "+l"(d) : "l"(a), "l"(b));
}
__device__ __forceinline__ unsigned long long pack2dup(float x) {
    unsigned long long r;
    asm("mov.b64 %0, {%1, %1};" : "=l"(r) : "f"(x));
    return r;
}
__device__ __forceinline__ float2 unpack2(unsigned long long v) {
    float lo, hi;
    asm("mov.b64 {%0, %1}, %2;" : "=f"(lo), "=f"(hi) : "l"(v));
    return make_float2(lo, hi);
}

// ---------------------------------------------------------------------------
// Kernel A: transpose conv1_w (OIHW) -> Wt[k][oc], k = (ky*3+kx)*256 + c
// ---------------------------------------------------------------------------
__global__ void k_transpose(const float* __restrict__ w) {
    int idx = blockIdx.x * blockDim.x + threadIdx.x;
    if (idx >= KTOT * COUT) return;
    int oc = idx / KTOT;
    int j  = idx % KTOT;
    int c  = j / 9;
    int ki = j % 9;
    g_Wt[(ki * CIN + c) * COUT + oc] = w[idx];
}

// ---------------------------------------------------------------------------
// Kernel B: conv1 3x3 SAME as tiled implicit GEMM. BM=BN=64, BK=16.
// Micro-tile: 4 rows x 2 col-pairs, packed f32x2 FMA (bit-exact per lane).
// Thread covers cols n0 + 2*tx + 32*jj + {0,1}, rows m0 + ty + 16*i.
// ---------------------------------------------------------------------------
__global__ void __launch_bounds__(256) k_conv1(const float* __restrict__ X,
                                               const float* __restrict__ bias) {
    __shared__ float As[16 * 64];
    __shared__ float Bs[16 * 64];

    int m0 = blockIdx.x * 64;
    int n0 = blockIdx.y * 64;
    int tid = threadIdx.x;
    int tx = tid & 15;
    int ty = tid >> 4;

    int py[4], px[4], pm[4];
    #pragma unroll
    for (int r = 0; r < 4; r++) {
        int e  = tid + 256 * r;
        int mm = e & 63;
        int p  = m0 + mm;
        pm[r] = mm;
        if (p < NPIX) { py[r] = p / FEAT_W; px[r] = p % FEAT_W; }
        else          { py[r] = -1000; px[r] = -1000; }
    }

    unsigned long long acc[4][2];
    #pragma unroll
    for (int i = 0; i < 4; i++) { acc[i][0] = 0ull; acc[i][1] = 0ull; }

    for (int kt = 0; kt < KTOT; kt += 16) {
        int ki = kt >> 8;
        int dy = ki / 3 - 1;
        int dx = ki % 3 - 1;
        int cbase = kt & 255;

        #pragma unroll
        for (int r = 0; r < 4; r++) {
            int e  = tid + 256 * r;
            int kk = e >> 6;
            int iy = py[r] + dy;
            int ix = px[r] + dx;
            float v = 0.0f;
            if (iy >= 0 && iy < FEAT_W && ix >= 0 && ix < FEAT_W)
                v = X[(cbase + kk) * NPIX + iy * FEAT_W + ix];
            As[kk * 64 + pm[r]] = v;
        }
        #pragma unroll
        for (int r = 0; r < 4; r++) {
            int e  = tid + 256 * r;
            int nn = e & 63;
            int kk = e >> 6;
            Bs[kk * 64 + nn] = g_Wt[(kt + kk) * COUT + n0 + nn];
        }
        __syncthreads();

        #pragma unroll
        for (int kk = 0; kk < 16; kk++) {
            unsigned long long b0 =
                *reinterpret_cast<const unsigned long long*>(&Bs[kk * 64 + 2 * tx]);
            unsigned long long b1 =
                *reinterpret_cast<const unsigned long long*>(&Bs[kk * 64 + 2 * tx + 32]);
            #pragma unroll
            for (int i = 0; i < 4; i++) {
                unsigned long long pa = pack2dup(As[kk * 64 + ty + 16 * i]);
                ffma2(acc[i][0], pa, b0);
                ffma2(acc[i][1], pa, b1);
            }
        }
        __syncthreads();
    }

    #pragma unroll
    for (int i = 0; i < 4; i++) {
        int p = m0 + ty + 16 * i;
        if (p >= NPIX) continue;
        #pragma unroll
        for (int jj = 0; jj < 2; jj++) {
            int n = n0 + 2 * tx + 32 * jj;
            float2 v = unpack2(acc[i][jj]);
            v.x += bias[n];
            v.y += bias[n + 1];
            *reinterpret_cast<float2*>(&g_h[p * COUT + n]) = v;
        }
    }
}

// ---------------------------------------------------------------------------
// Kernel C: heads as smem-staged GEMM (16 pixels/block) + decode + keys.
// dyn smem: W[54][257], bias[56], h[16][257], sv[16][57]
// ---------------------------------------------------------------------------
#define HPX 16
#define W_STRIDE 257
#define SV_STRIDE 57
#define SM_W    0
#define SM_BIAS (54 * W_STRIDE)                 // 13878
#define SM_H    (SM_BIAS + 56)                  // 13934
#define SM_SV   (SM_H + HPX * W_STRIDE)         // 18046
#define HEAD_SMEM ((SM_SV + HPX * SV_STRIDE) * 4)

__global__ void __launch_bounds__(256) k_head(const float* __restrict__ reg_w,
                                              const float* __restrict__ reg_b,
                                              const float* __restrict__ cls_w,
                                              const float* __restrict__ cls_b,
                                              float* __restrict__ out) {
    extern __shared__ float sm[];
    float* Wsh  = sm + SM_W;
    float* bsh  = sm + SM_BIAS;
    float* hsh  = sm + SM_H;
    float* sv   = sm + SM_SV;

    int tid = threadIdx.x;
    int p0 = blockIdx.x * HPX;

    // stage weights [54][256] -> padded smem
    for (int idx = tid; idx < 54 * 256; idx += 256) {
        int o = idx >> 8, c = idx & 255;
        float v = (o < 36) ? reg_w[o * 256 + c] : cls_w[(o - 36) * 256 + c];
        Wsh[o * W_STRIDE + c] = v;
    }
    if (tid < 54) bsh[tid] = (tid < 36) ? reg_b[tid] : cls_b[tid - 36];
    // stage h tile [16][256]
    for (int idx = tid; idx < HPX * 256; idx += 256) {
        int p = idx >> 8, c = idx & 255;
        hsh[p * W_STRIDE + c] = g_h[(p0 + p) * COUT + c];
    }
    __syncthreads();

    // compute sv[p][o] = dot(W[o], h[p]) + b[o]
    int p  = tid & 15;
    int ob = tid >> 4;
    #pragma unroll
    for (int t = 0; t < 4; t++) {
        int o = ob + 16 * t;
        if (o < 54) {
            const float* wr = Wsh + o * W_STRIDE;
            const float* hr = hsh + p * W_STRIDE;
            float acc = 0.0f;
            #pragma unroll 8
            for (int c = 0; c < 256; c++) acc = fmaf(wr[c], hr[c], acc);
            sv[p * SV_STRIDE + o] = acc + bsh[o];
        }
    }
    __syncthreads();

    // decode: 16 px x 9 anchors = 144 rows
    if (tid < HPX * NANCH) {
        int pl = tid / NANCH;
        int a  = tid % NANCH;
        int pg = p0 + pl;
        int y  = pg / FEAT_W;
        int xp = pg % FEAT_W;
        int row = pg * NANCH + a;
        const float* s = sv + pl * SV_STRIDE;
        float l0 = s[a * 4 + 0], l1 = s[a * 4 + 1];
        float l2 = s[a * 4 + 2], l3 = s[a * 4 + 3];
        float c0 = s[36 + a * 2 + 0];
        float c1 = s[36 + a * 2 + 1];

        float* locs = out + OFF_LOCS;
        float* clsO = out + OFF_CLS;
        float* objO = out + OFF_OBJ;
        float* cls2 = out + OFF_CLS2;
        locs[row * 4 + 0] = l0; locs[row * 4 + 1] = l1;
        locs[row * 4 + 2] = l2; locs[row * 4 + 3] = l3;
        clsO[row * 2 + 0] = c0; clsO[row * 2 + 1] = c1;
        cls2[row * 2 + 0] = c0; cls2[row * 2 + 1] = c1;
        objO[row] = c1;

        const double sr [3] = {0.7071067811865476, 1.0, 1.4142135623730951};
        const double sri[3] = {1.4142135623730951, 1.0, 0.7071067811865476};
        const double sc [3] = {4.0, 8.0, 16.0};
        double h2 = 2.0 * sc[a % 3] * sr [a / 3];
        double w2 = 2.0 * sc[a % 3] * sri[a / 3];
        double cyd = 4.0 * y + 2.0;
        double cxd = 4.0 * xp + 2.0;
        float y1 = (float)(cyd - h2), x1 = (float)(cxd - w2);
        float y2 = (float)(cyd + h2), x2 = (float)(cxd + w2);

        float ah = y2 - y1, aw = x2 - x1;
        float acy = fmaf(0.5f, ah, y1), acx = fmaf(0.5f, aw, x1);
        float dcy = fmaf(l0, ah, acy),  dcx = fmaf(l1, aw, acx);
        float hh = expf(l2) * ah, ww = expf(l3) * aw;
        float ry1 = fmaf(-0.5f, hh, dcy), rx1 = fmaf(-0.5f, ww, dcx);
        float ry2 = fmaf( 0.5f, hh, dcy), rx2 = fmaf( 0.5f, ww, dcx);
        ry1 = fminf(fmaxf(ry1, 0.0f), IMG_WF);
        rx1 = fminf(fmaxf(rx1, 0.0f), IMG_WF);
        ry2 = fminf(fmaxf(ry2, 0.0f), IMG_WF);
        rx2 = fminf(fmaxf(rx2, 0.0f), IMG_WF);
        float hs = ry2 - ry1, ws = rx2 - rx1;
        int valid = (hs >= MIN_SIZE) && (ws >= MIN_SIZE);

        g_roi[row] = make_float4(ry1, rx1, ry2, rx2);
        g_valid[row] = valid;

        float sc_m = valid ? c1 : __int_as_float(0xff800000);
        unsigned int u = __float_as_uint(sc_m);
        unsigned int k32 = u ^ ((u & 0x80000000u) ? 0xFFFFFFFFu : 0x80000000u);
        unsigned int dk = ~k32;  // ascending dk == descending score
        g_key[row] = ((unsigned long long)dk << 32) | (unsigned int)row;
    }
}

// ---------------------------------------------------------------------------
// Kernel I: per-replay init of g_rank and g_suppInit
// ---------------------------------------------------------------------------
__global__ void k_init() {
    int i = blockIdx.x * 256 + threadIdx.x;
    if (i < NROWS) g_rank[i] = 0;
    if (i < NWORDS)
        g_suppInit[i] = (i == NWORDS - 1) ? 0xFFFFFFFF00000000ull : 0ull;
}

// ---------------------------------------------------------------------------
// Kernel D1: partitioned rank. Block (jb, ib): j-chunk in smem, 1024 i's.
// ---------------------------------------------------------------------------
#define JC 3072
__global__ void __launch_bounds__(1024) k_rankpart() {
    __shared__ unsigned long long sk[JC];
    int tid = threadIdx.x;
    int j0 = blockIdx.x * JC;
    for (int j = tid; j < JC; j += 1024) {
        int gj = j0 + j;
        sk[j] = (gj < NROWS) ? g_key[gj] : ~0ull;   // pad > all real keys
    }
    __syncthreads();

    int i = blockIdx.y * 1024 + tid;
    if (i >= NROWS) return;
    unsigned long long my = g_key[i];
    const ulonglong2* sk2 = reinterpret_cast<const ulonglong2*>(sk);
    int r = 0;
    #pragma unroll 4
    for (int j = 0; j < JC / 2; j++) {
        ulonglong2 v = sk2[j];
        r += (v.x < my);
        r += (v.y < my);
    }
    atomicAdd(&g_rank[i], r);
}

// ---------------------------------------------------------------------------
// Kernel D2: scatter by rank + invalid bits
// ---------------------------------------------------------------------------
__global__ void k_scatter() {
    int i = blockIdx.x * 256 + threadIdx.x;
    if (i >= NROWS) return;
    int r = g_rank[i];
    if (r < PRE_NMS) {
        g_sorted[r] = g_roi[i];
        if (!g_valid[i])
            atomicOr(&g_suppInit[r >> 6], 1ull << (r & 63));
    }
}

// ---------------------------------------------------------------------------
// IoU helpers
// ---------------------------------------------------------------------------
__device__ __forceinline__ float box_area(float4 b) {
    return (b.w - b.y + 1.0f) * (b.z - b.x + 1.0f);
}
__device__ __forceinline__ bool iou_gt(float4 a, float aa, float4 b, float ab) {
    float yy1 = fmaxf(a.x, b.x), xx1 = fmaxf(a.y, b.y);
    float yy2 = fminf(a.z, b.z), xx2 = fminf(a.w, b.w);
    float inter = fmaxf(0.0f, xx2 - xx1 + 1.0f) * fmaxf(0.0f, yy2 - yy1 + 1.0f);
    float iou = inter / (aa + ab - inter);
    return iou > NMS_T;
}

// ---------------------------------------------------------------------------
// Kernel E1: pairwise IoU bitmask matrix (c >= r only).
// ---------------------------------------------------------------------------
__global__ void __launch_bounds__(256) k_mask() {
    __shared__ float4 RB[64], CB[64];
    __shared__ float  RA[64], CA[64];
    __shared__ unsigned long long MW[64];

    int c = blockIdx.x;
    int r = blockIdx.y;
    if (c < r) return;
    int tid = threadIdx.x;

    if (tid < 64) {
        float4 b = g_sorted[r * 64 + tid];
        RB[tid] = b; RA[tid] = box_area(b);
        MW[tid] = 0ull;
    } else if (tid < 128) {
        int t = tid - 64;
        float4 b = g_sorted[c * 64 + t];
        CB[t] = b; CA[t] = box_area(b);
    }
    __syncthreads();

    int l  = tid >> 2;
    int j0 = (tid & 3) * 16;
    int gi = r * 64 + l;
    float4 bl = RB[l];
    float  al = RA[l];
    unsigned long long bits = 0ull;
    #pragma unroll
    for (int jj = 0; jj < 16; jj++) {
        int j  = j0 + jj;
        int gj = c * 64 + j;
        if (gj > gi && iou_gt(bl, al, CB[j], CA[j]))
            bits |= 1ull << j;
    }
    if (bits) atomicOr(&MW[l], bits);
    __syncthreads();

    if (tid < 64)
        g_mask[(size_t)(r * 64 + tid) * NWORDS + c] = MW[tid];
}

// ---------------------------------------------------------------------------
// Kernel E2: greedy bitmask reduce (== reference lax.scan) + output scatter.
// Parallel suppression (kept-bit x word), diag double-buffer prefetch.
// ---------------------------------------------------------------------------
__global__ void __launch_bounds__(256) k_reduce(float* __restrict__ out) {
    __shared__ unsigned long long removed[NWORDS];
    __shared__ unsigned long long diagA[64], diagB[64];
    __shared__ int keepList[POST_NMS];
    __shared__ int keptBits[64];
    __shared__ int kcount, nKept;

    int tid = threadIdx.x;
    for (int w = tid; w < NWORDS; w += 256) removed[w] = g_suppInit[w];
    if (tid == 0) kcount = 0;
    if (tid < 64) diagA[tid] = g_mask[(size_t)tid * NWORDS + 0];
    __syncthreads();

    for (int w = 0; w < NWORDS; w++) {
        unsigned long long* diag  = (w & 1) ? diagB : diagA;
        unsigned long long* diagN = (w & 1) ? diagA : diagB;

        if (tid == 0) {
            unsigned long long rm = removed[w];
            int kc = kcount, nk = 0;
            for (int b = 0; b < 64 && kc < POST_NMS; b++) {
                if (!((rm >> b) & 1ull)) {
                    keepList[kc++] = w * 64 + b;
                    keptBits[nk++] = b;
                    rm |= diag[b];
                }
            }
            removed[w] = rm;
            kcount = kc;
            nKept = nk;
        }
        __syncthreads();
        if (kcount >= POST_NMS) break;

        // prefetch next diag into registers (latency hidden by suppression)
        unsigned long long dreg = 0ull;
        if (w + 1 < NWORDS && tid < 64)
            dreg = g_mask[(size_t)((w + 1) * 64 + tid) * NWORDS + (w + 1)];

        int nk = nKept;
        for (int k = 0; k < nk; k++) {
            int b = keptBits[k];
            const unsigned long long* mrow = &g_mask[(size_t)(w * 64 + b) * NWORDS];
            for (int w2 = w + 1 + tid; w2 < NWORDS; w2 += 256) {
                unsigned long long m = mrow[w2];
                if (m) atomicOr(&removed[w2], m);
            }
        }
        if (tid < 64) diagN[tid] = dreg;
        __syncthreads();
    }
    __syncthreads();

    int total = kcount;  // <= POST_NMS
    float* rois = out + OFF_ROIS;
    for (int k = tid; k < total; k += 256) {
        float4 bx = g_sorted[keepList[k]];
        rois[k * 4 + 0] = bx.x; rois[k * 4 + 1] = bx.y;
        rois[k * 4 + 2] = bx.z; rois[k * 4 + 3] = bx.w;
    }
    for (int i = total * 4 + tid; i < POST_NMS * 4; i += 256)
        rois[i] = 0.0f;
}

// ---------------------------------------------------------------------------
extern "C" void kernel_launch(void* const* d_in, const int* in_sizes, int n_in,
                              void* d_out, int out_size) {
    const float* x       = (const float*)d_in[0];
    const float* conv1_w = (const float*)d_in[1];
    const float* conv1_b = (const float*)d_in[2];
    const float* reg_w   = (const float*)d_in[3];
    const float* reg_b   = (const float*)d_in[4];
    const float* cls_w   = (const float*)d_in[5];
    const float* cls_b   = (const float*)d_in[6];
    float* out = (float*)d_out;

    cudaFuncSetAttribute(k_head, cudaFuncAttributeMaxDynamicSharedMemorySize, HEAD_SMEM);

    k_transpose<<<(KTOT * COUT + 255) / 256, 256>>>(conv1_w);
    k_conv1<<<dim3((NPIX + 63) / 64, COUT / 64), 256>>>(x, conv1_b);
    k_head<<<NPIX / HPX, 256, HEAD_SMEM>>>(reg_w, reg_b, cls_w, cls_b, out);
    k_init<<<(NROWS + 255) / 256, 256>>>();
    k_rankpart<<<dim3((NROWS + JC - 1) / JC, (NROWS + 1023) / 1024), 1024>>>();
    k_scatter<<<(NROWS + 255) / 256, 256>>>();
    k_mask<<<dim3(NWORDS, NWORDS), 256>>>();
    k_reduce<<<1, 256>>>(out);
}

// round 4
// speedup vs baseline: 7.5475x; 1.1198x over previous
#include <cuda_runtime.h>
#include <cuda_bf16.h>
#include <cstdint>

// ---------------------------------------------------------------------------
// RPN pipeline: conv3x3(256->256) -> 1x1 heads -> decode -> sort -> bitmask NMS
// ---------------------------------------------------------------------------

#define FEAT_W 52
#define NPIX   (FEAT_W * FEAT_W)          // 2704
#define CIN    256
#define COUT   256
#define KTOT   (9 * CIN)                  // 2304
#define NANCH  9
#define NROWS  (NPIX * NANCH)             // 24336
#define PRE_NMS 12000
#define NPAD    12032                     // PRE_NMS padded to mult of 64
#define NWORDS  188                      // NPAD/64
#define POST_NMS 2000
#define IMG_WF 210.0f
#define MIN_SIZE 16.0f
#define NMS_T 0.7f

// output layout (floats)
#define OFF_ROIS 0
#define OFF_LOCS 8000
#define OFF_CLS  105344
#define OFF_OBJ  154016
#define OFF_CLS2 178352

// -------------------- scratch (__device__ globals; no allocs) --------------
__device__ float  g_Wt[KTOT * COUT];          // k-major transposed weights
__device__ float  g_h[NPIX * COUT];           // conv1 output, pixel-major
__device__ float4 g_roi[NROWS];               // decoded clipped boxes
__device__ int    g_valid[NROWS];
__device__ unsigned long long g_key[NROWS];   // sortable keys (unique)
__device__ int    g_rank[NROWS];              // partial rank accumulators
__device__ float4 g_sorted[NPAD];             // top-12000 boxes by score
__device__ unsigned long long g_suppInit[NWORDS];
__device__ unsigned long long g_mask[(size_t)NPAD * NWORDS];  // 18.1 MB IoU bitmask

// -------------------- f32x2 packed-FMA helpers -----------------------------
__device__ __forceinline__ void ffma2(unsigned long long& d,
                                      unsigned long long a,
                                      unsigned long long b) {
    asm("fma.rn.f32x2 %0, %1, %2, %0;" : "+l"(d) : "l"(a), "l"(b));
}
__device__ __forceinline__ unsigned long long pack2dup(float x) {
    unsigned long long r;
    asm("mov.b64 %0, {%1, %1};" : "=l"(r) : "f"(x));
    return r;
}
__device__ __forceinline__ float2 unpack2(unsigned long long v) {
    float lo, hi;
    asm("mov.b64 {%0, %1}, %2;" : "=f"(lo), "=f"(hi) : "l"(v));
    return make_float2(lo, hi);
}

// ---------------------------------------------------------------------------
// Kernel A: smem-tiled transpose conv1_w (OIHW) -> Wt[k][oc], k=(ky*3+kx)*256+c
// Coalesced reads AND writes (32x32 tiles).
// ---------------------------------------------------------------------------
__global__ void __launch_bounds__(256) k_transpose(const float* __restrict__ w) {
    __shared__ float t[32][33];
    int j0  = blockIdx.x * 32;
    int oc0 = blockIdx.y * 32;
    int tx = threadIdx.x & 31;
    int ty = threadIdx.x >> 5;      // 0..7
    #pragma unroll
    for (int i = 0; i < 32; i += 8)
        t[ty + i][tx] = w[(oc0 + ty + i) * KTOT + j0 + tx];   // t[oc_l][j_l]
    __syncthreads();
    #pragma unroll
    for (int i = 0; i < 32; i += 8) {
        int j  = j0 + ty + i;
        int c  = j / 9;
        int ki = j % 9;
        g_Wt[(ki * CIN + c) * COUT + oc0 + tx] = t[tx][ty + i];
    }
}

// ---------------------------------------------------------------------------
// Kernel B: conv1 3x3 SAME as tiled implicit GEMM. BM=BN=64, BK=16.
// Packed f32x2 FMA micro-kernel (bit-exact per lane).
// ---------------------------------------------------------------------------
__global__ void __launch_bounds__(256) k_conv1(const float* __restrict__ X,
                                               const float* __restrict__ bias) {
    __shared__ float As[16 * 64];
    __shared__ float Bs[16 * 64];

    int m0 = blockIdx.x * 64;
    int n0 = blockIdx.y * 64;
    int tid = threadIdx.x;
    int tx = tid & 15;
    int ty = tid >> 4;

    int py[4], px[4], pm[4];
    #pragma unroll
    for (int r = 0; r < 4; r++) {
        int e  = tid + 256 * r;
        int mm = e & 63;
        int p  = m0 + mm;
        pm[r] = mm;
        if (p < NPIX) { py[r] = p / FEAT_W; px[r] = p % FEAT_W; }
        else          { py[r] = -1000; px[r] = -1000; }
    }

    unsigned long long acc[4][2];
    #pragma unroll
    for (int i = 0; i < 4; i++) { acc[i][0] = 0ull; acc[i][1] = 0ull; }

    for (int kt = 0; kt < KTOT; kt += 16) {
        int ki = kt >> 8;
        int dy = ki / 3 - 1;
        int dx = ki % 3 - 1;
        int cbase = kt & 255;

        #pragma unroll
        for (int r = 0; r < 4; r++) {
            int e  = tid + 256 * r;
            int kk = e >> 6;
            int iy = py[r] + dy;
            int ix = px[r] + dx;
            float v = 0.0f;
            if (iy >= 0 && iy < FEAT_W && ix >= 0 && ix < FEAT_W)
                v = X[(cbase + kk) * NPIX + iy * FEAT_W + ix];
            As[kk * 64 + pm[r]] = v;
        }
        #pragma unroll
        for (int r = 0; r < 4; r++) {
            int e  = tid + 256 * r;
            int nn = e & 63;
            int kk = e >> 6;
            Bs[kk * 64 + nn] = g_Wt[(kt + kk) * COUT + n0 + nn];
        }
        __syncthreads();

        #pragma unroll
        for (int kk = 0; kk < 16; kk++) {
            unsigned long long b0 =
                *reinterpret_cast<const unsigned long long*>(&Bs[kk * 64 + 2 * tx]);
            unsigned long long b1 =
                *reinterpret_cast<const unsigned long long*>(&Bs[kk * 64 + 2 * tx + 32]);
            #pragma unroll
            for (int i = 0; i < 4; i++) {
                unsigned long long pa = pack2dup(As[kk * 64 + ty + 16 * i]);
                ffma2(acc[i][0], pa, b0);
                ffma2(acc[i][1], pa, b1);
            }
        }
        __syncthreads();
    }

    #pragma unroll
    for (int i = 0; i < 4; i++) {
        int p = m0 + ty + 16 * i;
        if (p >= NPIX) continue;
        #pragma unroll
        for (int jj = 0; jj < 2; jj++) {
            int n = n0 + 2 * tx + 32 * jj;
            float2 v = unpack2(acc[i][jj]);
            v.x += bias[n];
            v.y += bias[n + 1];
            *reinterpret_cast<float2*>(&g_h[p * COUT + n]) = v;
        }
    }
}

// ---------------------------------------------------------------------------
// Kernel C: heads as smem-staged GEMM (16 pixels/block) + decode + keys.
// ---------------------------------------------------------------------------
#define HPX 16
#define W_STRIDE 257
#define SV_STRIDE 57
#define SM_W    0
#define SM_BIAS (54 * W_STRIDE)
#define SM_H    (SM_BIAS + 56)
#define SM_SV   (SM_H + HPX * W_STRIDE)
#define HEAD_SMEM ((SM_SV + HPX * SV_STRIDE) * 4)

__global__ void __launch_bounds__(256) k_head(const float* __restrict__ reg_w,
                                              const float* __restrict__ reg_b,
                                              const float* __restrict__ cls_w,
                                              const float* __restrict__ cls_b,
                                              float* __restrict__ out) {
    extern __shared__ float sm[];
    float* Wsh  = sm + SM_W;
    float* bsh  = sm + SM_BIAS;
    float* hsh  = sm + SM_H;
    float* sv   = sm + SM_SV;

    int tid = threadIdx.x;
    int p0 = blockIdx.x * HPX;

    for (int idx = tid; idx < 54 * 256; idx += 256) {
        int o = idx >> 8, c = idx & 255;
        float v = (o < 36) ? reg_w[o * 256 + c] : cls_w[(o - 36) * 256 + c];
        Wsh[o * W_STRIDE + c] = v;
    }
    if (tid < 54) bsh[tid] = (tid < 36) ? reg_b[tid] : cls_b[tid - 36];
    for (int idx = tid; idx < HPX * 256; idx += 256) {
        int p = idx >> 8, c = idx & 255;
        hsh[p * W_STRIDE + c] = g_h[(p0 + p) * COUT + c];
    }
    __syncthreads();

    int p  = tid & 15;
    int ob = tid >> 4;
    #pragma unroll
    for (int t = 0; t < 4; t++) {
        int o = ob + 16 * t;
        if (o < 54) {
            const float* wr = Wsh + o * W_STRIDE;
            const float* hr = hsh + p * W_STRIDE;
            float acc = 0.0f;
            #pragma unroll 8
            for (int c = 0; c < 256; c++) acc = fmaf(wr[c], hr[c], acc);
            sv[p * SV_STRIDE + o] = acc + bsh[o];
        }
    }
    __syncthreads();

    if (tid < HPX * NANCH) {
        int pl = tid / NANCH;
        int a  = tid % NANCH;
        int pg = p0 + pl;
        int y  = pg / FEAT_W;
        int xp = pg % FEAT_W;
        int row = pg * NANCH + a;
        const float* s = sv + pl * SV_STRIDE;
        float l0 = s[a * 4 + 0], l1 = s[a * 4 + 1];
        float l2 = s[a * 4 + 2], l3 = s[a * 4 + 3];
        float c0 = s[36 + a * 2 + 0];
        float c1 = s[36 + a * 2 + 1];

        float* locs = out + OFF_LOCS;
        float* clsO = out + OFF_CLS;
        float* objO = out + OFF_OBJ;
        float* cls2 = out + OFF_CLS2;
        locs[row * 4 + 0] = l0; locs[row * 4 + 1] = l1;
        locs[row * 4 + 2] = l2; locs[row * 4 + 3] = l3;
        clsO[row * 2 + 0] = c0; clsO[row * 2 + 1] = c1;
        cls2[row * 2 + 0] = c0; cls2[row * 2 + 1] = c1;
        objO[row] = c1;

        const double sr [3] = {0.7071067811865476, 1.0, 1.4142135623730951};
        const double sri[3] = {1.4142135623730951, 1.0, 0.7071067811865476};
        const double sc [3] = {4.0, 8.0, 16.0};
        double h2 = 2.0 * sc[a % 3] * sr [a / 3];
        double w2 = 2.0 * sc[a % 3] * sri[a / 3];
        double cyd = 4.0 * y + 2.0;
        double cxd = 4.0 * xp + 2.0;
        float y1 = (float)(cyd - h2), x1 = (float)(cxd - w2);
        float y2 = (float)(cyd + h2), x2 = (float)(cxd + w2);

        float ah = y2 - y1, aw = x2 - x1;
        float acy = fmaf(0.5f, ah, y1), acx = fmaf(0.5f, aw, x1);
        float dcy = fmaf(l0, ah, acy),  dcx = fmaf(l1, aw, acx);
        float hh = expf(l2) * ah, ww = expf(l3) * aw;
        float ry1 = fmaf(-0.5f, hh, dcy), rx1 = fmaf(-0.5f, ww, dcx);
        float ry2 = fmaf( 0.5f, hh, dcy), rx2 = fmaf( 0.5f, ww, dcx);
        ry1 = fminf(fmaxf(ry1, 0.0f), IMG_WF);
        rx1 = fminf(fmaxf(rx1, 0.0f), IMG_WF);
        ry2 = fminf(fmaxf(ry2, 0.0f), IMG_WF);
        rx2 = fminf(fmaxf(rx2, 0.0f), IMG_WF);
        float hs = ry2 - ry1, ws = rx2 - rx1;
        int valid = (hs >= MIN_SIZE) && (ws >= MIN_SIZE);

        g_roi[row] = make_float4(ry1, rx1, ry2, rx2);
        g_valid[row] = valid;

        float sc_m = valid ? c1 : __int_as_float(0xff800000);
        unsigned int u = __float_as_uint(sc_m);
        unsigned int k32 = u ^ ((u & 0x80000000u) ? 0xFFFFFFFFu : 0x80000000u);
        unsigned int dk = ~k32;  // ascending dk == descending score
        g_key[row] = ((unsigned long long)dk << 32) | (unsigned int)row;
    }
}

// ---------------------------------------------------------------------------
// Kernel I: per-replay init
// ---------------------------------------------------------------------------
__global__ void k_init() {
    int i = blockIdx.x * 256 + threadIdx.x;
    if (i < NROWS) g_rank[i] = 0;
    if (i < NWORDS)
        g_suppInit[i] = (i == NWORDS - 1) ? 0xFFFFFFFF00000000ull : 0ull;
}

// ---------------------------------------------------------------------------
// Kernel D1: partitioned rank
// ---------------------------------------------------------------------------
#define JC 3072
__global__ void __launch_bounds__(1024) k_rankpart() {
    __shared__ unsigned long long sk[JC];
    int tid = threadIdx.x;
    int j0 = blockIdx.x * JC;
    for (int j = tid; j < JC; j += 1024) {
        int gj = j0 + j;
        sk[j] = (gj < NROWS) ? g_key[gj] : ~0ull;
    }
    __syncthreads();

    int i = blockIdx.y * 1024 + tid;
    if (i >= NROWS) return;
    unsigned long long my = g_key[i];
    const ulonglong2* sk2 = reinterpret_cast<const ulonglong2*>(sk);
    int r = 0;
    #pragma unroll 4
    for (int j = 0; j < JC / 2; j++) {
        ulonglong2 v = sk2[j];
        r += (v.x < my);
        r += (v.y < my);
    }
    atomicAdd(&g_rank[i], r);
}

// ---------------------------------------------------------------------------
// Kernel D2: scatter by rank + invalid bits
// ---------------------------------------------------------------------------
__global__ void k_scatter() {
    int i = blockIdx.x * 256 + threadIdx.x;
    if (i >= NROWS) return;
    int r = g_rank[i];
    if (r < PRE_NMS) {
        g_sorted[r] = g_roi[i];
        if (!g_valid[i])
            atomicOr(&g_suppInit[r >> 6], 1ull << (r & 63));
    }
}

// ---------------------------------------------------------------------------
// IoU helpers
// ---------------------------------------------------------------------------
__device__ __forceinline__ float box_area(float4 b) {
    return (b.w - b.y + 1.0f) * (b.z - b.x + 1.0f);
}
__device__ __forceinline__ bool iou_gt(float4 a, float aa, float4 b, float ab) {
    float yy1 = fmaxf(a.x, b.x), xx1 = fmaxf(a.y, b.y);
    float yy2 = fminf(a.z, b.z), xx2 = fminf(a.w, b.w);
    float inter = fmaxf(0.0f, xx2 - xx1 + 1.0f) * fmaxf(0.0f, yy2 - yy1 + 1.0f);
    float iou = inter / (aa + ab - inter);
    return iou > NMS_T;
}

// ---------------------------------------------------------------------------
// Kernel E1: pairwise IoU bitmask matrix (c >= r only).
// ---------------------------------------------------------------------------
__global__ void __launch_bounds__(256) k_mask() {
    __shared__ float4 RB[64], CB[64];
    __shared__ float  RA[64], CA[64];
    __shared__ unsigned long long MW[64];

    int c = blockIdx.x;
    int r = blockIdx.y;
    if (c < r) return;
    int tid = threadIdx.x;

    if (tid < 64) {
        float4 b = g_sorted[r * 64 + tid];
        RB[tid] = b; RA[tid] = box_area(b);
        MW[tid] = 0ull;
    } else if (tid < 128) {
        int t = tid - 64;
        float4 b = g_sorted[c * 64 + t];
        CB[t] = b; CA[t] = box_area(b);
    }
    __syncthreads();

    int l  = tid >> 2;
    int j0 = (tid & 3) * 16;
    int gi = r * 64 + l;
    float4 bl = RB[l];
    float  al = RA[l];
    unsigned long long bits = 0ull;
    #pragma unroll
    for (int jj = 0; jj < 16; jj++) {
        int j  = j0 + jj;
        int gj = c * 64 + j;
        if (gj > gi && iou_gt(bl, al, CB[j], CA[j]))
            bits |= 1ull << j;
    }
    if (bits) atomicOr(&MW[l], bits);
    __syncthreads();

    if (tid < 64)
        g_mask[(size_t)(r * 64 + tid) * NWORDS + c] = MW[tid];
}

// ---------------------------------------------------------------------------
// Kernel E2: greedy bitmask reduce (== reference lax.scan), latency-optimized.
// Warp0: cooperative resolve (diag in registers, ffs+shfl). All 8 warps:
// kept-parallel suppression (warp = kept-row slot, lanes = word stripe).
// ---------------------------------------------------------------------------
__global__ void __launch_bounds__(256) k_reduce(float* __restrict__ out) {
    __shared__ unsigned long long removed[NWORDS];
    __shared__ int keepList[POST_NMS];
    __shared__ int keptBits[64];
    __shared__ int kcountSh, nKeptSh;

    int tid  = threadIdx.x;
    int lane = tid & 31;
    int warp = tid >> 5;

    for (int w = tid; w < NWORDS; w += 256) removed[w] = g_suppInit[w];
    if (tid == 0) kcountSh = 0;

    // diag registers for word 0 (warp0 lanes: bits lane and lane+32)
    unsigned long long dlo = 0, dhi = 0;
    if (warp == 0) {
        dlo = g_mask[(size_t)lane * NWORDS + 0];
        dhi = g_mask[(size_t)(lane + 32) * NWORDS + 0];
    }
    __syncthreads();

    for (int w = 0; w < NWORDS; w++) {
        // ---- resolve word w (warp0, lockstep-uniform) ----
        if (warp == 0) {
            unsigned long long rm = removed[w];
            unsigned long long kept = 0ull;
            int kc = kcountSh;
            while (kc < POST_NMS) {
                unsigned long long avail = ~rm;
                if (!avail) break;
                int b = __ffsll((long long)avail) - 1;
                kept |= 1ull << b;
                if (lane == 0) keepList[kc] = w * 64 + b;
                kc++;
                unsigned long long d = (b < 32)
                    ? __shfl_sync(0xFFFFFFFFu, dlo, b)
                    : __shfl_sync(0xFFFFFFFFu, dhi, b - 32);
                rm |= d | (1ull << b);
            }
            if (lane == 0) {
                removed[w] = rm;
                kcountSh = kc;
                nKeptSh = __popcll(kept);
            }
            // compact kept bits (each lane handles bits lane, lane+32)
            if ((kept >> lane) & 1ull)
                keptBits[__popcll(kept & ((1ull << lane) - 1ull))] = lane;
            int l2 = lane + 32;
            if ((kept >> l2) & 1ull)
                keptBits[(int)__popcll(kept & ((1ull << l2) - 1ull))] = l2;
        }
        __syncthreads();
        if (kcountSh >= POST_NMS) break;

        // ---- prefetch next diag into registers (overlaps suppression) ----
        unsigned long long ndlo = 0, ndhi = 0;
        if (warp == 0 && w + 1 < NWORDS) {
            ndlo = g_mask[(size_t)((w + 1) * 64 + lane) * NWORDS + (w + 1)];
            ndhi = g_mask[(size_t)((w + 1) * 64 + lane + 32) * NWORDS + (w + 1)];
        }

        // ---- kept-parallel suppression of later words ----
        int nk = nKeptSh;
        for (int kb = warp; kb < nk; kb += 8) {
            int b = keptBits[kb];
            const unsigned long long* mrow =
                &g_mask[(size_t)(w * 64 + b) * NWORDS];
            for (int w2 = w + 1 + lane; w2 < NWORDS; w2 += 32) {
                unsigned long long m = mrow[w2];
                if (m) atomicOr(&removed[w2], m);
            }
        }
        if (warp == 0) { dlo = ndlo; dhi = ndhi; }
        __syncthreads();
    }
    __syncthreads();

    int total = kcountSh;  // <= POST_NMS
    float* rois = out + OFF_ROIS;
    for (int k = tid; k < total; k += 256) {
        float4 bx = g_sorted[keepList[k]];
        rois[k * 4 + 0] = bx.x; rois[k * 4 + 1] = bx.y;
        rois[k * 4 + 2] = bx.z; rois[k * 4 + 3] = bx.w;
    }
    for (int i = total * 4 + tid; i < POST_NMS * 4; i += 256)
        rois[i] = 0.0f;
}

// ---------------------------------------------------------------------------
extern "C" void kernel_launch(void* const* d_in, const int* in_sizes, int n_in,
                              void* d_out, int out_size) {
    const float* x       = (const float*)d_in[0];
    const float* conv1_w = (const float*)d_in[1];
    const float* conv1_b = (const float*)d_in[2];
    const float* reg_w   = (const float*)d_in[3];
    const float* reg_b   = (const float*)d_in[4];
    const float* cls_w   = (const float*)d_in[5];
    const float* cls_b   = (const float*)d_in[6];
    float* out = (float*)d_out;

    cudaFuncSetAttribute(k_head, cudaFuncAttributeMaxDynamicSharedMemorySize, HEAD_SMEM);

    k_transpose<<<dim3(KTOT / 32, COUT / 32), 256>>>(conv1_w);
    k_conv1<<<dim3((NPIX + 63) / 64, COUT / 64), 256>>>(x, conv1_b);
    k_head<<<NPIX / HPX, 256, HEAD_SMEM>>>(reg_w, reg_b, cls_w, cls_b, out);
    k_init<<<(NROWS + 255) / 256, 256>>>();
    k_rankpart<<<dim3((NROWS + JC - 1) / JC, (NROWS + 1023) / 1024), 1024>>>();
    k_scatter<<<(NROWS + 255) / 256, 256>>>();
    k_mask<<<dim3(NWORDS, NWORDS), 256>>>();
    k_reduce<<<1, 256>>>(out);
}

// round 5
// speedup vs baseline: 8.0352x; 1.0646x over previous
#include <cuda_runtime.h>
#include <cuda_bf16.h>
#include <cstdint>

// ---------------------------------------------------------------------------
// RPN pipeline: conv3x3(256->256) -> 1x1 heads -> decode -> hist-sort -> NMS
// ---------------------------------------------------------------------------

#define FEAT_W 52
#define NPIX   (FEAT_W * FEAT_W)          // 2704
#define CIN    256
#define COUT   256
#define KTOT   (9 * CIN)                  // 2304
#define NANCH  9
#define NROWS  (NPIX * NANCH)             // 24336
#define PRE_NMS 12000
#define NPAD    12032
#define NWORDS  188
#define POST_NMS 2000
#define IMG_WF 210.0f
#define MIN_SIZE 16.0f
#define NMS_T 0.7f
#define NBINS 16384
#define NIW   381                          // ceil(NROWS/64)

// output layout (floats)
#define OFF_ROIS 0
#define OFF_LOCS 8000
#define OFF_CLS  105344
#define OFF_OBJ  154016
#define OFF_CLS2 178352

// -------------------- scratch (__device__ globals; no allocs) --------------
__device__ float  g_Wt[KTOT * COUT];
__device__ float  g_h[NPIX * COUT];
__device__ float4 g_roi[NROWS];
__device__ unsigned long long g_key[NROWS];
__device__ unsigned long long g_bk[NROWS];     // bucketed keys (valid only)
__device__ int    g_binBase[NBINS + 1];        // [NBINS] = V (valid count)
__device__ unsigned long long g_invW[NIW];     // invalid bitmap
__device__ int    g_invBase[NIW];              // exclusive popc scan
__device__ float4 g_sorted[NPAD];
__device__ unsigned long long g_suppInit[NWORDS];
__device__ unsigned long long g_mask[(size_t)NPAD * NWORDS];

// -------------------- f32x2 packed-FMA helpers -----------------------------
__device__ __forceinline__ void ffma2(unsigned long long& d,
                                      unsigned long long a,
                                      unsigned long long b) {
    asm("fma.rn.f32x2 %0, %1, %2, %0;" : "+l"(d) : "l"(a), "l"(b));
}
__device__ __forceinline__ unsigned long long pack2dup(float x) {
    unsigned long long r;
    asm("mov.b64 %0, {%1, %1};" : "=l"(r) : "f"(x));
    return r;
}
__device__ __forceinline__ float2 unpack2(unsigned long long v) {
    float lo, hi;
    asm("mov.b64 {%0, %1}, %2;" : "=f"(lo), "=f"(hi) : "l"(v));
    return make_float2(lo, hi);
}

// ---------------------------------------------------------------------------
// slot 1: clear suppInit (phantom rows 12000..12031 pre-suppressed)
// ---------------------------------------------------------------------------
__global__ void k_zero() {
    int t = threadIdx.x;
    if (t < NWORDS)
        g_suppInit[t] = (t == NWORDS - 1) ? 0xFFFFFFFF00000000ull : 0ull;
}

// ---------------------------------------------------------------------------
// slots 2,3: smem-tiled weight transpose, split in two halves (oc dimension)
// ---------------------------------------------------------------------------
__global__ void __launch_bounds__(256) k_transpose(const float* __restrict__ w,
                                                   int half) {
    __shared__ float t[32][33];
    int j0  = blockIdx.x * 32;
    int oc0 = (half * 4 + blockIdx.y) * 32;
    int tx = threadIdx.x & 31;
    int ty = threadIdx.x >> 5;
    #pragma unroll
    for (int i = 0; i < 32; i += 8)
        t[ty + i][tx] = w[(oc0 + ty + i) * KTOT + j0 + tx];
    __syncthreads();
    #pragma unroll
    for (int i = 0; i < 32; i += 8) {
        int j  = j0 + ty + i;
        int c  = j / 9;
        int ki = j % 9;
        g_Wt[(ki * CIN + c) * COUT + oc0 + tx] = t[tx][ty + i];
    }
}

// ---------------------------------------------------------------------------
// slot 4 (PROFILED): conv1 implicit GEMM, BM=BN=64, BK=16, f32x2 FMA.
// A-tile stored pre-duplicated {v,v} to remove per-kk MOVs.
// ---------------------------------------------------------------------------
__global__ void __launch_bounds__(256) k_conv1(const float* __restrict__ X,
                                               const float* __restrict__ bias) {
    __shared__ unsigned long long As2[16 * 64];   // 8 KB, {v,v} pairs
    __shared__ float Bs[16 * 64];                 // 4 KB

    int m0 = blockIdx.x * 64;
    int n0 = blockIdx.y * 64;
    int tid = threadIdx.x;
    int tx = tid & 15;
    int ty = tid >> 4;

    int py[4], px[4], pm[4];
    #pragma unroll
    for (int r = 0; r < 4; r++) {
        int e  = tid + 256 * r;
        int mm = e & 63;
        int p  = m0 + mm;
        pm[r] = mm;
        if (p < NPIX) { py[r] = p / FEAT_W; px[r] = p % FEAT_W; }
        else          { py[r] = -1000; px[r] = -1000; }
    }

    unsigned long long acc[4][2];
    #pragma unroll
    for (int i = 0; i < 4; i++) { acc[i][0] = 0ull; acc[i][1] = 0ull; }

    for (int kt = 0; kt < KTOT; kt += 16) {
        int ki = kt >> 8;
        int dy = ki / 3 - 1;
        int dx = ki % 3 - 1;
        int cbase = kt & 255;

        #pragma unroll
        for (int r = 0; r < 4; r++) {
            int e  = tid + 256 * r;
            int kk = e >> 6;
            int iy = py[r] + dy;
            int ix = px[r] + dx;
            float v = 0.0f;
            if (iy >= 0 && iy < FEAT_W && ix >= 0 && ix < FEAT_W)
                v = X[(cbase + kk) * NPIX + iy * FEAT_W + ix];
            As2[kk * 64 + pm[r]] = pack2dup(v);
        }
        #pragma unroll
        for (int r = 0; r < 4; r++) {
            int e  = tid + 256 * r;
            int nn = e & 63;
            int kk = e >> 6;
            Bs[kk * 64 + nn] = g_Wt[(kt + kk) * COUT + n0 + nn];
        }
        __syncthreads();

        #pragma unroll
        for (int kk = 0; kk < 16; kk++) {
            unsigned long long b0 =
                *reinterpret_cast<const unsigned long long*>(&Bs[kk * 64 + 2 * tx]);
            unsigned long long b1 =
                *reinterpret_cast<const unsigned long long*>(&Bs[kk * 64 + 2 * tx + 32]);
            #pragma unroll
            for (int i = 0; i < 4; i++) {
                unsigned long long pa = As2[kk * 64 + ty + 16 * i];
                ffma2(acc[i][0], pa, b0);
                ffma2(acc[i][1], pa, b1);
            }
        }
        __syncthreads();
    }

    #pragma unroll
    for (int i = 0; i < 4; i++) {
        int p = m0 + ty + 16 * i;
        if (p >= NPIX) continue;
        #pragma unroll
        for (int jj = 0; jj < 2; jj++) {
            int n = n0 + 2 * tx + 32 * jj;
            float2 v = unpack2(acc[i][jj]);
            v.x += bias[n];
            v.y += bias[n + 1];
            *reinterpret_cast<float2*>(&g_h[p * COUT + n]) = v;
        }
    }
}

// ---------------------------------------------------------------------------
// slot 5: heads as smem-staged GEMM (16 pixels/block) + decode + keys
// ---------------------------------------------------------------------------
#define HPX 16
#define W_STRIDE 257
#define SV_STRIDE 57
#define SM_W    0
#define SM_BIAS (54 * W_STRIDE)
#define SM_H    (SM_BIAS + 56)
#define SM_SV   (SM_H + HPX * W_STRIDE)
#define HEAD_SMEM ((SM_SV + HPX * SV_STRIDE) * 4)

__global__ void __launch_bounds__(256) k_head(const float* __restrict__ reg_w,
                                              const float* __restrict__ reg_b,
                                              const float* __restrict__ cls_w,
                                              const float* __restrict__ cls_b,
                                              float* __restrict__ out) {
    extern __shared__ float sm[];
    float* Wsh  = sm + SM_W;
    float* bsh  = sm + SM_BIAS;
    float* hsh  = sm + SM_H;
    float* sv   = sm + SM_SV;

    int tid = threadIdx.x;
    int p0 = blockIdx.x * HPX;

    for (int idx = tid; idx < 54 * 256; idx += 256) {
        int o = idx >> 8, c = idx & 255;
        float v = (o < 36) ? reg_w[o * 256 + c] : cls_w[(o - 36) * 256 + c];
        Wsh[o * W_STRIDE + c] = v;
    }
    if (tid < 54) bsh[tid] = (tid < 36) ? reg_b[tid] : cls_b[tid - 36];
    for (int idx = tid; idx < HPX * 256; idx += 256) {
        int p = idx >> 8, c = idx & 255;
        hsh[p * W_STRIDE + c] = g_h[(p0 + p) * COUT + c];
    }
    __syncthreads();

    int p  = tid & 15;
    int ob = tid >> 4;
    #pragma unroll
    for (int t = 0; t < 4; t++) {
        int o = ob + 16 * t;
        if (o < 54) {
            const float* wr = Wsh + o * W_STRIDE;
            const float* hr = hsh + p * W_STRIDE;
            float acc = 0.0f;
            #pragma unroll 8
            for (int c = 0; c < 256; c++) acc = fmaf(wr[c], hr[c], acc);
            sv[p * SV_STRIDE + o] = acc + bsh[o];
        }
    }
    __syncthreads();

    if (tid < HPX * NANCH) {
        int pl = tid / NANCH;
        int a  = tid % NANCH;
        int pg = p0 + pl;
        int y  = pg / FEAT_W;
        int xp = pg % FEAT_W;
        int row = pg * NANCH + a;
        const float* s = sv + pl * SV_STRIDE;
        float l0 = s[a * 4 + 0], l1 = s[a * 4 + 1];
        float l2 = s[a * 4 + 2], l3 = s[a * 4 + 3];
        float c0 = s[36 + a * 2 + 0];
        float c1 = s[36 + a * 2 + 1];

        float* locs = out + OFF_LOCS;
        float* clsO = out + OFF_CLS;
        float* objO = out + OFF_OBJ;
        float* cls2 = out + OFF_CLS2;
        locs[row * 4 + 0] = l0; locs[row * 4 + 1] = l1;
        locs[row * 4 + 2] = l2; locs[row * 4 + 3] = l3;
        clsO[row * 2 + 0] = c0; clsO[row * 2 + 1] = c1;
        cls2[row * 2 + 0] = c0; cls2[row * 2 + 1] = c1;
        objO[row] = c1;

        const double sr [3] = {0.7071067811865476, 1.0, 1.4142135623730951};
        const double sri[3] = {1.4142135623730951, 1.0, 0.7071067811865476};
        const double sc [3] = {4.0, 8.0, 16.0};
        double h2 = 2.0 * sc[a % 3] * sr [a / 3];
        double w2 = 2.0 * sc[a % 3] * sri[a / 3];
        double cyd = 4.0 * y + 2.0;
        double cxd = 4.0 * xp + 2.0;
        float y1 = (float)(cyd - h2), x1 = (float)(cxd - w2);
        float y2 = (float)(cyd + h2), x2 = (float)(cxd + w2);

        float ah = y2 - y1, aw = x2 - x1;
        float acy = fmaf(0.5f, ah, y1), acx = fmaf(0.5f, aw, x1);
        float dcy = fmaf(l0, ah, acy),  dcx = fmaf(l1, aw, acx);
        float hh = expf(l2) * ah, ww = expf(l3) * aw;
        float ry1 = fmaf(-0.5f, hh, dcy), rx1 = fmaf(-0.5f, ww, dcx);
        float ry2 = fmaf( 0.5f, hh, dcy), rx2 = fmaf( 0.5f, ww, dcx);
        ry1 = fminf(fmaxf(ry1, 0.0f), IMG_WF);
        rx1 = fminf(fmaxf(rx1, 0.0f), IMG_WF);
        ry2 = fminf(fmaxf(ry2, 0.0f), IMG_WF);
        rx2 = fminf(fmaxf(rx2, 0.0f), IMG_WF);
        float hs = ry2 - ry1, ws = rx2 - rx1;
        int valid = (hs >= MIN_SIZE) && (ws >= MIN_SIZE);

        g_roi[row] = make_float4(ry1, rx1, ry2, rx2);

        float sc_m = valid ? c1 : __int_as_float(0xff800000);
        unsigned int u = __float_as_uint(sc_m);
        unsigned int k32 = u ^ ((u & 0x80000000u) ? 0xFFFFFFFFu : 0x80000000u);
        unsigned int dk = ~k32;  // ascending dk == descending score
        // invalid rows: dk == 0xff800000 exactly (only -inf maps there)
        g_key[row] = ((unsigned long long)dk << 32) | (unsigned int)row;
    }
}

// ---------------------------------------------------------------------------
// slot 6: single-block histogram + scans + bucketing (counting sort phase 1)
// smem: hist[16384] int, inv[NIW] u64 (padded), part[1024] int  ~= 73 KB
// ---------------------------------------------------------------------------
#define NIW_PAD 384
#define PREP_SMEM (NBINS * 4 + NIW_PAD * 8 + 1024 * 4)

__global__ void __launch_bounds__(1024) k_prep() {
    extern __shared__ int smi[];
    int* hist = smi;                                            // NBINS
    unsigned long long* inv = (unsigned long long*)(smi + NBINS);  // NIW_PAD
    int* part = (int*)(inv + NIW_PAD);                          // 1024

    int tid = threadIdx.x;
    for (int b = tid; b < NBINS; b += 1024) hist[b] = 0;
    if (tid < NIW_PAD) inv[tid] = 0ull;
    __syncthreads();

    for (int i = tid; i < NROWS; i += 1024) {
        unsigned int dk = (unsigned int)(g_key[i] >> 32);
        if (dk < 0xff800000u) atomicAdd(&hist[dk >> 18], 1);
        else atomicOr(&inv[i >> 6], 1ull << (i & 63));
    }
    __syncthreads();

    // invalid bitmap popc scan (exclusive per word)
    int pv = (tid < NIW) ? __popcll(inv[tid]) : 0;
    part[tid] = pv;
    __syncthreads();
    for (int off = 1; off < 1024; off <<= 1) {
        int v = part[tid];
        int u = (tid >= off) ? part[tid - off] : 0;
        __syncthreads();
        part[tid] = v + u;
        __syncthreads();
    }
    int totalInv = part[1023];
    if (tid < NIW) {
        g_invBase[tid] = (tid ? part[tid - 1] : 0);
        g_invW[tid] = inv[tid];
    }
    __syncthreads();

    // histogram exclusive scan (16 bins per thread + block scan)
    int base16 = tid * 16;
    int loc[16];
    int s = 0;
    #pragma unroll
    for (int k = 0; k < 16; k++) { loc[k] = s; s += hist[base16 + k]; }
    part[tid] = s;
    __syncthreads();
    for (int off = 1; off < 1024; off <<= 1) {
        int v = part[tid];
        int u = (tid >= off) ? part[tid - off] : 0;
        __syncthreads();
        part[tid] = v + u;
        __syncthreads();
    }
    int tbase = (tid ? part[tid - 1] : 0);
    __syncthreads();
    #pragma unroll
    for (int k = 0; k < 16; k++) {
        int bb = tbase + loc[k];
        g_binBase[base16 + k] = bb;
        hist[base16 + k] = bb;     // reuse as bucket cursor
    }
    if (tid == 0) g_binBase[NBINS] = NROWS - totalInv;   // V
    __syncthreads();

    // bucket valid keys (order within bin arbitrary; full key is unique)
    for (int i = tid; i < NROWS; i += 1024) {
        unsigned long long key = g_key[i];
        unsigned int dk = (unsigned int)(key >> 32);
        if (dk < 0xff800000u) {
            int slot = atomicAdd(&hist[dk >> 18], 1);
            g_bk[slot] = key;
        }
    }
}

// ---------------------------------------------------------------------------
// slot 7: exact stable rank within tiny bins + scatter top-12000
// ---------------------------------------------------------------------------
__global__ void k_rank2() {
    int t = blockIdx.x * 256 + threadIdx.x;
    if (t >= NROWS) return;
    int V = g_binBase[NBINS];

    if (t < V) {   // valid element at bucket slot t
        unsigned long long key = g_bk[t];
        unsigned int p = ((unsigned int)(key >> 32)) >> 18;
        int lo = g_binBase[p];
        int hi = g_binBase[p + 1];
        int r = lo;
        for (int j = lo; j < hi; j++) r += (g_bk[j] < key);
        if (r < PRE_NMS) {
            int row = (int)(key & 0xffffffffu);
            g_sorted[r] = g_roi[row];
        }
    }
    // invalid role: row t
    unsigned long long w = g_invW[t >> 6];
    if ((w >> (t & 63)) & 1ull) {
        int r = V + g_invBase[t >> 6] +
                (int)__popcll(w & ((1ull << (t & 63)) - 1ull));
        if (r < PRE_NMS) {
            g_sorted[r] = g_roi[t];
            atomicOr(&g_suppInit[r >> 6], 1ull << (r & 63));
        }
    }
}

// ---------------------------------------------------------------------------
// IoU helpers
// ---------------------------------------------------------------------------
__device__ __forceinline__ float box_area(float4 b) {
    return (b.w - b.y + 1.0f) * (b.z - b.x + 1.0f);
}
__device__ __forceinline__ bool iou_gt(float4 a, float aa, float4 b, float ab) {
    float yy1 = fmaxf(a.x, b.x), xx1 = fmaxf(a.y, b.y);
    float yy2 = fminf(a.z, b.z), xx2 = fminf(a.w, b.w);
    float inter = fmaxf(0.0f, xx2 - xx1 + 1.0f) * fmaxf(0.0f, yy2 - yy1 + 1.0f);
    float iou = inter / (aa + ab - inter);
    return iou > NMS_T;
}

// ---------------------------------------------------------------------------
// slot 8: pairwise IoU bitmask matrix (c >= r only)
// ---------------------------------------------------------------------------
__global__ void __launch_bounds__(256) k_mask() {
    __shared__ float4 RB[64], CB[64];
    __shared__ float  RA[64], CA[64];
    __shared__ unsigned long long MW[64];

    int c = blockIdx.x;
    int r = blockIdx.y;
    if (c < r) return;
    int tid = threadIdx.x;

    if (tid < 64) {
        float4 b = g_sorted[r * 64 + tid];
        RB[tid] = b; RA[tid] = box_area(b);
        MW[tid] = 0ull;
    } else if (tid < 128) {
        int t = tid - 64;
        float4 b = g_sorted[c * 64 + t];
        CB[t] = b; CA[t] = box_area(b);
    }
    __syncthreads();

    int l  = tid >> 2;
    int j0 = (tid & 3) * 16;
    int gi = r * 64 + l;
    float4 bl = RB[l];
    float  al = RA[l];
    unsigned long long bits = 0ull;
    #pragma unroll
    for (int jj = 0; jj < 16; jj++) {
        int j  = j0 + jj;
        int gj = c * 64 + j;
        if (gj > gi && iou_gt(bl, al, CB[j], CA[j]))
            bits |= 1ull << j;
    }
    if (bits) atomicOr(&MW[l], bits);
    __syncthreads();

    if (tid < 64)
        g_mask[(size_t)(r * 64 + tid) * NWORDS + c] = MW[tid];
}

// ---------------------------------------------------------------------------
// slot 9: greedy bitmask reduce (== reference lax.scan) + output scatter
// ---------------------------------------------------------------------------
__global__ void __launch_bounds__(256) k_reduce(float* __restrict__ out) {
    __shared__ unsigned long long removed[NWORDS];
    __shared__ int keepList[POST_NMS];
    __shared__ int keptBits[64];
    __shared__ int kcountSh, nKeptSh;

    int tid  = threadIdx.x;
    int lane = tid & 31;
    int warp = tid >> 5;

    for (int w = tid; w < NWORDS; w += 256) removed[w] = g_suppInit[w];
    if (tid == 0) kcountSh = 0;

    unsigned long long dlo = 0, dhi = 0;
    if (warp == 0) {
        dlo = g_mask[(size_t)lane * NWORDS + 0];
        dhi = g_mask[(size_t)(lane + 32) * NWORDS + 0];
    }
    __syncthreads();

    for (int w = 0; w < NWORDS; w++) {
        if (warp == 0) {
            unsigned long long rm = removed[w];
            unsigned long long kept = 0ull;
            int kc = kcountSh;
            while (kc < POST_NMS) {
                unsigned long long avail = ~rm;
                if (!avail) break;
                int b = __ffsll((long long)avail) - 1;
                kept |= 1ull << b;
                if (lane == 0) keepList[kc] = w * 64 + b;
                kc++;
                unsigned long long d = (b < 32)
                    ? __shfl_sync(0xFFFFFFFFu, dlo, b)
                    : __shfl_sync(0xFFFFFFFFu, dhi, b - 32);
                rm |= d | (1ull << b);
            }
            if (lane == 0) {
                removed[w] = rm;
                kcountSh = kc;
                nKeptSh = __popcll(kept);
            }
            if ((kept >> lane) & 1ull)
                keptBits[__popcll(kept & ((1ull << lane) - 1ull))] = lane;
            int l2 = lane + 32;
            if ((kept >> l2) & 1ull)
                keptBits[(int)__popcll(kept & ((1ull << l2) - 1ull))] = l2;
        }
        __syncthreads();
        if (kcountSh >= POST_NMS) break;

        unsigned long long ndlo = 0, ndhi = 0;
        if (warp == 0 && w + 1 < NWORDS) {
            ndlo = g_mask[(size_t)((w + 1) * 64 + lane) * NWORDS + (w + 1)];
            ndhi = g_mask[(size_t)((w + 1) * 64 + lane + 32) * NWORDS + (w + 1)];
        }

        int nk = nKeptSh;
        for (int kb = warp; kb < nk; kb += 8) {
            int b = keptBits[kb];
            const unsigned long long* mrow =
                &g_mask[(size_t)(w * 64 + b) * NWORDS];
            for (int w2 = w + 1 + lane; w2 < NWORDS; w2 += 32) {
                unsigned long long m = mrow[w2];
                if (m) atomicOr(&removed[w2], m);
            }
        }
        if (warp == 0) { dlo = ndlo; dhi = ndhi; }
        __syncthreads();
    }
    __syncthreads();

    int total = kcountSh;
    float* rois = out + OFF_ROIS;
    for (int k = tid; k < total; k += 256) {
        float4 bx = g_sorted[keepList[k]];
        rois[k * 4 + 0] = bx.x; rois[k * 4 + 1] = bx.y;
        rois[k * 4 + 2] = bx.z; rois[k * 4 + 3] = bx.w;
    }
    for (int i = total * 4 + tid; i < POST_NMS * 4; i += 256)
        rois[i] = 0.0f;
}

// ---------------------------------------------------------------------------
extern "C" void kernel_launch(void* const* d_in, const int* in_sizes, int n_in,
                              void* d_out, int out_size) {
    const float* x       = (const float*)d_in[0];
    const float* conv1_w = (const float*)d_in[1];
    const float* conv1_b = (const float*)d_in[2];
    const float* reg_w   = (const float*)d_in[3];
    const float* reg_b   = (const float*)d_in[4];
    const float* cls_w   = (const float*)d_in[5];
    const float* cls_b   = (const float*)d_in[6];
    float* out = (float*)d_out;

    cudaFuncSetAttribute(k_head, cudaFuncAttributeMaxDynamicSharedMemorySize, HEAD_SMEM);
    cudaFuncSetAttribute(k_prep, cudaFuncAttributeMaxDynamicSharedMemorySize, PREP_SMEM);

    k_zero<<<1, 256>>>();
    k_transpose<<<dim3(KTOT / 32, 4), 256>>>(conv1_w, 0);
    k_transpose<<<dim3(KTOT / 32, 4), 256>>>(conv1_w, 1);
    k_conv1<<<dim3((NPIX + 63) / 64, COUT / 64), 256>>>(x, conv1_b);   // slot 4: profiled
    k_head<<<NPIX / HPX, 256, HEAD_SMEM>>>(reg_w, reg_b, cls_w, cls_b, out);
    k_prep<<<1, 1024, PREP_SMEM>>>();
    k_rank2<<<(NROWS + 255) / 256, 256>>>();
    k_mask<<<dim3(NWORDS, NWORDS), 256>>>();
    k_reduce<<<1, 256>>>(out);
}

// round 6
// speedup vs baseline: 10.9918x; 1.3680x over previous
#include <cuda_runtime.h>
#include <cuda_bf16.h>
#include <cstdint>

// ---------------------------------------------------------------------------
// RPN pipeline: conv3x3(256->256) -> 1x1 heads -> decode -> hist-sort -> NMS
// ---------------------------------------------------------------------------

#define FEAT_W 52
#define NPIX   (FEAT_W * FEAT_W)          // 2704
#define CIN    256
#define COUT   256
#define KTOT   (9 * CIN)                  // 2304
#define NANCH  9
#define NROWS  (NPIX * NANCH)             // 24336
#define PRE_NMS 12000
#define NPAD    12032
#define NWORDS  188
#define POST_NMS 2000
#define IMG_WF 210.0f
#define MIN_SIZE 16.0f
#define NMS_T 0.7f
#define NBINS 16384
#define NIW   381

// output layout (floats)
#define OFF_ROIS 0
#define OFF_LOCS 8000
#define OFF_CLS  105344
#define OFF_OBJ  154016
#define OFF_CLS2 178352

// -------------------- scratch (__device__ globals; no allocs) --------------
__device__ float  g_Wt[KTOT * COUT];
__device__ float  g_h[NPIX * COUT];
__device__ float4 g_roi[NROWS];
__device__ unsigned long long g_key[NROWS];
__device__ unsigned long long g_bk[NROWS];
__device__ int    g_binBase[NBINS + 1];
__device__ unsigned long long g_invW[NIW];
__device__ int    g_invBase[NIW];
__device__ float4 g_sorted[NPAD];
__device__ unsigned long long g_suppInit[NWORDS];
__device__ unsigned long long g_mask[(size_t)NPAD * NWORDS];

// -------------------- f32x2 packed-FMA helpers -----------------------------
__device__ __forceinline__ void ffma2(unsigned long long& d,
                                      unsigned long long a,
                                      unsigned long long b) {
    asm("fma.rn.f32x2 %0, %1, %2, %0;" : "+l"(d) : "l"(a), "l"(b));
}
__device__ __forceinline__ unsigned long long pack2dup(float x) {
    unsigned long long r;
    asm("mov.b64 %0, {%1, %1};" : "=l"(r) : "f"(x));
    return r;
}
__device__ __forceinline__ float2 unpack2(unsigned long long v) {
    float lo, hi;
    asm("mov.b64 {%0, %1}, %2;" : "=f"(lo), "=f"(hi) : "l"(v));
    return make_float2(lo, hi);
}

// ---------------------------------------------------------------------------
// slots 1,2: smem-tiled weight transpose halves; half 0 also inits suppInit
// ---------------------------------------------------------------------------
__global__ void __launch_bounds__(256) k_transpose(const float* __restrict__ w,
                                                   int half) {
    if (half == 0 && blockIdx.x == 0 && blockIdx.y == 0) {
        int t = threadIdx.x;
        if (t < NWORDS)
            g_suppInit[t] = (t == NWORDS - 1) ? 0xFFFFFFFF00000000ull : 0ull;
    }
    __shared__ float t[32][33];
    int j0  = blockIdx.x * 32;
    int oc0 = (half * 4 + blockIdx.y) * 32;
    int tx = threadIdx.x & 31;
    int ty = threadIdx.x >> 5;
    #pragma unroll
    for (int i = 0; i < 32; i += 8)
        t[ty + i][tx] = w[(oc0 + ty + i) * KTOT + j0 + tx];
    __syncthreads();
    #pragma unroll
    for (int i = 0; i < 32; i += 8) {
        int j  = j0 + ty + i;
        int c  = j / 9;
        int ki = j % 9;
        g_Wt[(ki * CIN + c) * COUT + oc0 + tx] = t[tx][ty + i];
    }
}

// ---------------------------------------------------------------------------
// slot 3: conv1 implicit GEMM. BM=32, BN=64, BK=16, 256 thr, f32x2 FMA.
// grid 85x4 = 340 blocks (~2.3 CTA/SM) to fix grid-limited occupancy.
// Per-lane accumulation order identical to all prior rounds (k ascending).
// ---------------------------------------------------------------------------
__global__ void __launch_bounds__(256) k_conv1(const float* __restrict__ X,
                                               const float* __restrict__ bias) {
    __shared__ unsigned long long As2[16 * 32];   // 4 KB {v,v} pairs
    __shared__ __align__(16) float Bs[16 * 64];   // 4 KB

    int m0 = blockIdx.x * 32;
    int n0 = blockIdx.y * 64;
    int tid = threadIdx.x;
    int tx = tid & 15;
    int ty = tid >> 4;

    // A-tile loader coords: 2 elements/thread
    int py[2], px[2], pm[2];
    #pragma unroll
    for (int r = 0; r < 2; r++) {
        int e  = tid + 256 * r;
        int mm = e & 31;
        int p  = m0 + mm;
        pm[r] = mm;
        if (p < NPIX) { py[r] = p / FEAT_W; px[r] = p % FEAT_W; }
        else          { py[r] = -1000; px[r] = -1000; }
    }

    unsigned long long acc[2][2];
    acc[0][0] = acc[0][1] = acc[1][0] = acc[1][1] = 0ull;

    for (int kt = 0; kt < KTOT; kt += 16) {
        int ki = kt >> 8;
        int dy = ki / 3 - 1;
        int dx = ki % 3 - 1;
        int cbase = kt & 255;

        #pragma unroll
        for (int r = 0; r < 2; r++) {
            int e  = tid + 256 * r;
            int kk = e >> 5;
            int iy = py[r] + dy;
            int ix = px[r] + dx;
            float v = 0.0f;
            if (iy >= 0 && iy < FEAT_W && ix >= 0 && ix < FEAT_W)
                v = X[(cbase + kk) * NPIX + iy * FEAT_W + ix];
            As2[kk * 32 + pm[r]] = pack2dup(v);
        }
        #pragma unroll
        for (int r = 0; r < 4; r++) {
            int e  = tid + 256 * r;
            int nn = e & 63;
            int kk = e >> 6;
            Bs[kk * 64 + nn] = g_Wt[(kt + kk) * COUT + n0 + nn];
        }
        __syncthreads();

        const unsigned long long* Bs64 =
            reinterpret_cast<const unsigned long long*>(Bs);
        #pragma unroll
        for (int kk = 0; kk < 16; kk++) {
            unsigned long long pa0 = As2[kk * 32 + ty];
            unsigned long long pa1 = As2[kk * 32 + ty + 16];
            unsigned long long b0  = Bs64[kk * 32 + tx];
            unsigned long long b1  = Bs64[kk * 32 + tx + 16];
            ffma2(acc[0][0], pa0, b0);
            ffma2(acc[0][1], pa0, b1);
            ffma2(acc[1][0], pa1, b0);
            ffma2(acc[1][1], pa1, b1);
        }
        __syncthreads();
    }

    #pragma unroll
    for (int i = 0; i < 2; i++) {
        int p = m0 + ty + 16 * i;
        if (p >= NPIX) continue;
        #pragma unroll
        for (int jj = 0; jj < 2; jj++) {
            int n = n0 + 2 * tx + 32 * jj;
            float2 v = unpack2(acc[i][jj]);
            v.x += bias[n];
            v.y += bias[n + 1];
            *reinterpret_cast<float2*>(&g_h[p * COUT + n]) = v;
        }
    }
}

// ---------------------------------------------------------------------------
// slot 4 (PROFILED): heads as smem-staged GEMM (16 px/block) + decode + keys
// ---------------------------------------------------------------------------
#define HPX 16
#define W_STRIDE 257
#define SV_STRIDE 57
#define SM_W    0
#define SM_BIAS (54 * W_STRIDE)
#define SM_H    (SM_BIAS + 56)
#define SM_SV   (SM_H + HPX * W_STRIDE)
#define HEAD_SMEM ((SM_SV + HPX * SV_STRIDE) * 4)

__global__ void __launch_bounds__(256) k_head(const float* __restrict__ reg_w,
                                              const float* __restrict__ reg_b,
                                              const float* __restrict__ cls_w,
                                              const float* __restrict__ cls_b,
                                              float* __restrict__ out) {
    extern __shared__ float sm[];
    float* Wsh  = sm + SM_W;
    float* bsh  = sm + SM_BIAS;
    float* hsh  = sm + SM_H;
    float* sv   = sm + SM_SV;

    int tid = threadIdx.x;
    int p0 = blockIdx.x * HPX;

    for (int idx = tid; idx < 54 * 256; idx += 256) {
        int o = idx >> 8, c = idx & 255;
        float v = (o < 36) ? reg_w[o * 256 + c] : cls_w[(o - 36) * 256 + c];
        Wsh[o * W_STRIDE + c] = v;
    }
    if (tid < 54) bsh[tid] = (tid < 36) ? reg_b[tid] : cls_b[tid - 36];
    for (int idx = tid; idx < HPX * 256; idx += 256) {
        int p = idx >> 8, c = idx & 255;
        hsh[p * W_STRIDE + c] = g_h[(p0 + p) * COUT + c];
    }
    __syncthreads();

    int p  = tid & 15;
    int ob = tid >> 4;
    #pragma unroll
    for (int t = 0; t < 4; t++) {
        int o = ob + 16 * t;
        if (o < 54) {
            const float* wr = Wsh + o * W_STRIDE;
            const float* hr = hsh + p * W_STRIDE;
            float acc = 0.0f;
            #pragma unroll 8
            for (int c = 0; c < 256; c++) acc = fmaf(wr[c], hr[c], acc);
            sv[p * SV_STRIDE + o] = acc + bsh[o];
        }
    }
    __syncthreads();

    if (tid < HPX * NANCH) {
        int pl = tid / NANCH;
        int a  = tid % NANCH;
        int pg = p0 + pl;
        int y  = pg / FEAT_W;
        int xp = pg % FEAT_W;
        int row = pg * NANCH + a;
        const float* s = sv + pl * SV_STRIDE;
        float l0 = s[a * 4 + 0], l1 = s[a * 4 + 1];
        float l2 = s[a * 4 + 2], l3 = s[a * 4 + 3];
        float c0 = s[36 + a * 2 + 0];
        float c1 = s[36 + a * 2 + 1];

        float* locs = out + OFF_LOCS;
        float* clsO = out + OFF_CLS;
        float* objO = out + OFF_OBJ;
        float* cls2 = out + OFF_CLS2;
        locs[row * 4 + 0] = l0; locs[row * 4 + 1] = l1;
        locs[row * 4 + 2] = l2; locs[row * 4 + 3] = l3;
        clsO[row * 2 + 0] = c0; clsO[row * 2 + 1] = c1;
        cls2[row * 2 + 0] = c0; cls2[row * 2 + 1] = c1;
        objO[row] = c1;

        const double sr [3] = {0.7071067811865476, 1.0, 1.4142135623730951};
        const double sri[3] = {1.4142135623730951, 1.0, 0.7071067811865476};
        const double sc [3] = {4.0, 8.0, 16.0};
        double h2 = 2.0 * sc[a % 3] * sr [a / 3];
        double w2 = 2.0 * sc[a % 3] * sri[a / 3];
        double cyd = 4.0 * y + 2.0;
        double cxd = 4.0 * xp + 2.0;
        float y1 = (float)(cyd - h2), x1 = (float)(cxd - w2);
        float y2 = (float)(cyd + h2), x2 = (float)(cxd + w2);

        float ah = y2 - y1, aw = x2 - x1;
        float acy = fmaf(0.5f, ah, y1), acx = fmaf(0.5f, aw, x1);
        float dcy = fmaf(l0, ah, acy),  dcx = fmaf(l1, aw, acx);
        float hh = expf(l2) * ah, ww = expf(l3) * aw;
        float ry1 = fmaf(-0.5f, hh, dcy), rx1 = fmaf(-0.5f, ww, dcx);
        float ry2 = fmaf( 0.5f, hh, dcy), rx2 = fmaf( 0.5f, ww, dcx);
        ry1 = fminf(fmaxf(ry1, 0.0f), IMG_WF);
        rx1 = fminf(fmaxf(rx1, 0.0f), IMG_WF);
        ry2 = fminf(fmaxf(ry2, 0.0f), IMG_WF);
        rx2 = fminf(fmaxf(rx2, 0.0f), IMG_WF);
        float hs = ry2 - ry1, ws = rx2 - rx1;
        int valid = (hs >= MIN_SIZE) && (ws >= MIN_SIZE);

        g_roi[row] = make_float4(ry1, rx1, ry2, rx2);

        float sc_m = valid ? c1 : __int_as_float(0xff800000);
        unsigned int u = __float_as_uint(sc_m);
        unsigned int k32 = u ^ ((u & 0x80000000u) ? 0xFFFFFFFFu : 0x80000000u);
        unsigned int dk = ~k32;
        g_key[row] = ((unsigned long long)dk << 32) | (unsigned int)row;
    }
}

// ---------------------------------------------------------------------------
// slot 5: single-block histogram + scans + bucketing
// ---------------------------------------------------------------------------
#define NIW_PAD 384
#define PREP_SMEM (NBINS * 4 + NIW_PAD * 8 + 1024 * 4)

__global__ void __launch_bounds__(1024) k_prep() {
    extern __shared__ int smi[];
    int* hist = smi;
    unsigned long long* inv = (unsigned long long*)(smi + NBINS);
    int* part = (int*)(inv + NIW_PAD);

    int tid = threadIdx.x;
    for (int b = tid; b < NBINS; b += 1024) hist[b] = 0;
    if (tid < NIW_PAD) inv[tid] = 0ull;
    __syncthreads();

    for (int i = tid; i < NROWS; i += 1024) {
        unsigned int dk = (unsigned int)(g_key[i] >> 32);
        if (dk < 0xff800000u) atomicAdd(&hist[dk >> 18], 1);
        else atomicOr(&inv[i >> 6], 1ull << (i & 63));
    }
    __syncthreads();

    int pv = (tid < NIW) ? __popcll(inv[tid]) : 0;
    part[tid] = pv;
    __syncthreads();
    for (int off = 1; off < 1024; off <<= 1) {
        int v = part[tid];
        int u = (tid >= off) ? part[tid - off] : 0;
        __syncthreads();
        part[tid] = v + u;
        __syncthreads();
    }
    int totalInv = part[1023];
    if (tid < NIW) {
        g_invBase[tid] = (tid ? part[tid - 1] : 0);
        g_invW[tid] = inv[tid];
    }
    __syncthreads();

    int base16 = tid * 16;
    int loc[16];
    int s = 0;
    #pragma unroll
    for (int k = 0; k < 16; k++) { loc[k] = s; s += hist[base16 + k]; }
    part[tid] = s;
    __syncthreads();
    for (int off = 1; off < 1024; off <<= 1) {
        int v = part[tid];
        int u = (tid >= off) ? part[tid - off] : 0;
        __syncthreads();
        part[tid] = v + u;
        __syncthreads();
    }
    int tbase = (tid ? part[tid - 1] : 0);
    __syncthreads();
    #pragma unroll
    for (int k = 0; k < 16; k++) {
        int bb = tbase + loc[k];
        g_binBase[base16 + k] = bb;
        hist[base16 + k] = bb;
    }
    if (tid == 0) g_binBase[NBINS] = NROWS - totalInv;
    __syncthreads();

    for (int i = tid; i < NROWS; i += 1024) {
        unsigned long long key = g_key[i];
        unsigned int dk = (unsigned int)(key >> 32);
        if (dk < 0xff800000u) {
            int slot = atomicAdd(&hist[dk >> 18], 1);
            g_bk[slot] = key;
        }
    }
}

// ---------------------------------------------------------------------------
// slot 6: exact stable rank within bins + scatter top-12000
// ---------------------------------------------------------------------------
__global__ void k_rank2() {
    int t = blockIdx.x * 256 + threadIdx.x;
    if (t >= NROWS) return;
    int V = g_binBase[NBINS];

    if (t < V) {
        unsigned long long key = g_bk[t];
        unsigned int p = ((unsigned int)(key >> 32)) >> 18;
        int lo = g_binBase[p];
        int hi = g_binBase[p + 1];
        int r = lo;
        for (int j = lo; j < hi; j++) r += (g_bk[j] < key);
        if (r < PRE_NMS) {
            int row = (int)(key & 0xffffffffu);
            g_sorted[r] = g_roi[row];
        }
    }
    unsigned long long w = g_invW[t >> 6];
    if ((w >> (t & 63)) & 1ull) {
        int r = V + g_invBase[t >> 6] +
                (int)__popcll(w & ((1ull << (t & 63)) - 1ull));
        if (r < PRE_NMS) {
            g_sorted[r] = g_roi[t];
            atomicOr(&g_suppInit[r >> 6], 1ull << (r & 63));
        }
    }
}

// ---------------------------------------------------------------------------
// IoU helpers
// ---------------------------------------------------------------------------
__device__ __forceinline__ float box_area(float4 b) {
    return (b.w - b.y + 1.0f) * (b.z - b.x + 1.0f);
}
__device__ __forceinline__ bool iou_gt(float4 a, float aa, float4 b, float ab) {
    float yy1 = fmaxf(a.x, b.x), xx1 = fmaxf(a.y, b.y);
    float yy2 = fminf(a.z, b.z), xx2 = fminf(a.w, b.w);
    float inter = fmaxf(0.0f, xx2 - xx1 + 1.0f) * fmaxf(0.0f, yy2 - yy1 + 1.0f);
    float iou = inter / (aa + ab - inter);
    return iou > NMS_T;
}

// ---------------------------------------------------------------------------
// slot 7: pairwise IoU bitmask matrix (c >= r only)
// ---------------------------------------------------------------------------
__global__ void __launch_bounds__(256) k_mask() {
    __shared__ float4 RB[64], CB[64];
    __shared__ float  RA[64], CA[64];
    __shared__ unsigned long long MW[64];

    int c = blockIdx.x;
    int r = blockIdx.y;
    if (c < r) return;
    int tid = threadIdx.x;

    if (tid < 64) {
        float4 b = g_sorted[r * 64 + tid];
        RB[tid] = b; RA[tid] = box_area(b);
        MW[tid] = 0ull;
    } else if (tid < 128) {
        int t = tid - 64;
        float4 b = g_sorted[c * 64 + t];
        CB[t] = b; CA[t] = box_area(b);
    }
    __syncthreads();

    int l  = tid >> 2;
    int j0 = (tid & 3) * 16;
    int gi = r * 64 + l;
    float4 bl = RB[l];
    float  al = RA[l];
    unsigned long long bits = 0ull;
    #pragma unroll
    for (int jj = 0; jj < 16; jj++) {
        int j  = j0 + jj;
        int gj = c * 64 + j;
        if (gj > gi && iou_gt(bl, al, CB[j], CA[j]))
            bits |= 1ull << j;
    }
    if (bits) atomicOr(&MW[l], bits);
    __syncthreads();

    if (tid < 64)
        g_mask[(size_t)(r * 64 + tid) * NWORDS + c] = MW[tid];
}

// ---------------------------------------------------------------------------
// slot 8: greedy bitmask reduce (== reference lax.scan), 1024 threads.
// Warp0 resolves; suppression: 8 kept-slots x 128-word stripes in one round.
// ---------------------------------------------------------------------------
__global__ void __launch_bounds__(1024) k_reduce(float* __restrict__ out) {
    __shared__ unsigned long long removed[NWORDS];
    __shared__ int keepList[POST_NMS];
    __shared__ int keptBits[64];
    __shared__ int kcountSh, nKeptSh;

    int tid  = threadIdx.x;
    int lane = tid & 31;
    int warp = tid >> 5;

    for (int w = tid; w < NWORDS; w += 1024) removed[w] = g_suppInit[w];
    if (tid == 0) kcountSh = 0;

    unsigned long long dlo = 0, dhi = 0;
    if (warp == 0) {
        dlo = g_mask[(size_t)lane * NWORDS + 0];
        dhi = g_mask[(size_t)(lane + 32) * NWORDS + 0];
    }
    __syncthreads();

    for (int w = 0; w < NWORDS; w++) {
        if (warp == 0) {
            unsigned long long rm = removed[w];
            unsigned long long kept = 0ull;
            int kc = kcountSh;
            while (kc < POST_NMS) {
                unsigned long long avail = ~rm;
                if (!avail) break;
                int b = __ffsll((long long)avail) - 1;
                kept |= 1ull << b;
                if (lane == 0) keepList[kc] = w * 64 + b;
                kc++;
                unsigned long long d = (b < 32)
                    ? __shfl_sync(0xFFFFFFFFu, dlo, b)
                    : __shfl_sync(0xFFFFFFFFu, dhi, b - 32);
                rm |= d | (1ull << b);
            }
            if (lane == 0) {
                removed[w] = rm;
                kcountSh = kc;
                nKeptSh = __popcll(kept);
            }
            if ((kept >> lane) & 1ull)
                keptBits[__popcll(kept & ((1ull << lane) - 1ull))] = lane;
            int l2 = lane + 32;
            if ((kept >> l2) & 1ull)
                keptBits[(int)__popcll(kept & ((1ull << l2) - 1ull))] = l2;
        }
        __syncthreads();
        if (kcountSh >= POST_NMS) break;

        unsigned long long ndlo = 0, ndhi = 0;
        if (warp == 0 && w + 1 < NWORDS) {
            ndlo = g_mask[(size_t)((w + 1) * 64 + lane) * NWORDS + (w + 1)];
            ndhi = g_mask[(size_t)((w + 1) * 64 + lane + 32) * NWORDS + (w + 1)];
        }

        // 32 warps = 8 kept-slots (warp>>2) x 4 sub-stripes (warp&3)
        int nk = nKeptSh;
        int slot = warp >> 2;
        int sub  = warp & 3;
        for (int kb = slot; kb < nk; kb += 8) {
            int b = keptBits[kb];
            const unsigned long long* mrow =
                &g_mask[(size_t)(w * 64 + b) * NWORDS];
            for (int w2 = w + 1 + sub * 32 + lane; w2 < NWORDS; w2 += 128) {
                unsigned long long m = mrow[w2];
                if (m) atomicOr(&removed[w2], m);
            }
        }
        if (warp == 0) { dlo = ndlo; dhi = ndhi; }
        __syncthreads();
    }
    __syncthreads();

    int total = kcountSh;
    float* rois = out + OFF_ROIS;
    for (int k = tid; k < total; k += 1024) {
        float4 bx = g_sorted[keepList[k]];
        rois[k * 4 + 0] = bx.x; rois[k * 4 + 1] = bx.y;
        rois[k * 4 + 2] = bx.z; rois[k * 4 + 3] = bx.w;
    }
    for (int i = total * 4 + tid; i < POST_NMS * 4; i += 1024)
        rois[i] = 0.0f;
}

// ---------------------------------------------------------------------------
extern "C" void kernel_launch(void* const* d_in, const int* in_sizes, int n_in,
                              void* d_out, int out_size) {
    const float* x       = (const float*)d_in[0];
    const float* conv1_w = (const float*)d_in[1];
    const float* conv1_b = (const float*)d_in[2];
    const float* reg_w   = (const float*)d_in[3];
    const float* reg_b   = (const float*)d_in[4];
    const float* cls_w   = (const float*)d_in[5];
    const float* cls_b   = (const float*)d_in[6];
    float* out = (float*)d_out;

    cudaFuncSetAttribute(k_head, cudaFuncAttributeMaxDynamicSharedMemorySize, HEAD_SMEM);
    cudaFuncSetAttribute(k_prep, cudaFuncAttributeMaxDynamicSharedMemorySize, PREP_SMEM);

    k_transpose<<<dim3(KTOT / 32, 4), 256>>>(conv1_w, 0);
    k_transpose<<<dim3(KTOT / 32, 4), 256>>>(conv1_w, 1);
    k_conv1<<<dim3((NPIX + 31) / 32, COUT / 64), 256>>>(x, conv1_b);
    k_head<<<NPIX / HPX, 256, HEAD_SMEM>>>(reg_w, reg_b, cls_w, cls_b, out);  // slot 4
    k_prep<<<1, 1024, PREP_SMEM>>>();
    k_rank2<<<(NROWS + 255) / 256, 256>>>();
    k_mask<<<dim3(NWORDS, NWORDS), 256>>>();
    k_reduce<<<1, 1024>>>(out);
}